// round 4
// baseline (speedup 1.0000x reference)
#include <cuda_runtime.h>
#include <cuda_bf16.h>
#include <cstdint>

#define BATCH 2
#define SEQ 2048
#define DIM 1024
#define NHEADS 16
#define HDIM 64
#define SM_SCALE 0.125f
#define MROWS 4096           // B*L
#define KP 3072              // packed K' = 3*DIM
#define NCH 48               // KP / 64

// ---------------------------------------------------------------------------
// Scratch (device globals: allocation-free)
// ---------------------------------------------------------------------------
__device__ __align__(16) __nv_bfloat16 g_xp [(size_t)MROWS * KP];    // x packed (hi|lo|hi)
__device__ __align__(16) __nv_bfloat16 g_wqp[(size_t)3 * DIM * KP];  // w_qkv    (hi|hi|lo)
__device__ __align__(16) __nv_bfloat16 g_wpp[(size_t)DIM * KP];      // w_proj   (hi|hi|lo)
__device__ __align__(16) __nv_bfloat16 g_aop[(size_t)MROWS * KP];    // attn out (hi|lo|hi)

// per-head Q/K/V, bf16 hi/lo, layout [b][h][l][64]
#define QKV_ELEMS ((size_t)BATCH * NHEADS * SEQ * HDIM)
__device__ __align__(16) __nv_bfloat16 g_qh[QKV_ELEMS];
__device__ __align__(16) __nv_bfloat16 g_ql[QKV_ELEMS];
__device__ __align__(16) __nv_bfloat16 g_kh[QKV_ELEMS];
__device__ __align__(16) __nv_bfloat16 g_kl[QKV_ELEMS];
__device__ __align__(16) __nv_bfloat16 g_vh[QKV_ELEMS];
__device__ __align__(16) __nv_bfloat16 g_vl[QKV_ELEMS];

// ---------------------------------------------------------------------------
// Base-ISA helpers
// ---------------------------------------------------------------------------
__device__ __forceinline__ uint32_t smem_u32(const void* p) {
    uint32_t a;
    asm("{ .reg .u64 t; cvta.to.shared.u64 t, %1; cvt.u32.u64 %0, t; }"
        : "=r"(a) : "l"(p));
    return a;
}
__device__ __forceinline__ void ldsm4(uint32_t* r, uint32_t a) {
    asm volatile("ldmatrix.sync.aligned.m8n8.x4.shared.b16 {%0,%1,%2,%3}, [%4];"
        : "=r"(r[0]), "=r"(r[1]), "=r"(r[2]), "=r"(r[3]) : "r"(a));
}
__device__ __forceinline__ void ldsm4t(uint32_t* r, uint32_t a) {
    asm volatile("ldmatrix.sync.aligned.m8n8.x4.trans.shared.b16 {%0,%1,%2,%3}, [%4];"
        : "=r"(r[0]), "=r"(r[1]), "=r"(r[2]), "=r"(r[3]) : "r"(a));
}
__device__ __forceinline__ void mma_bf16(float* c, const uint32_t* a, const uint32_t* b) {
    asm volatile(
        "mma.sync.aligned.m16n8k16.row.col.f32.bf16.bf16.f32 "
        "{%0,%1,%2,%3}, {%4,%5,%6,%7}, {%8,%9}, {%0,%1,%2,%3};"
        : "+f"(c[0]), "+f"(c[1]), "+f"(c[2]), "+f"(c[3])
        : "r"(a[0]), "r"(a[1]), "r"(a[2]), "r"(a[3]), "r"(b[0]), "r"(b[1]));
}
#define CPA16(d, s) \
    asm volatile("cp.async.cg.shared.global [%0], [%1], 16;" :: "r"(d), "l"(s))
#define CP_COMMIT() asm volatile("cp.async.commit_group;" ::: "memory")

__device__ __forceinline__ uint32_t pack2bf(float x, float y) {
    __nv_bfloat162 t = __float22bfloat162_rn(make_float2(x, y));
    return *reinterpret_cast<uint32_t*>(&t);
}
__device__ __forceinline__ uint32_t packresid(uint32_t hp, float x, float y) {
    float hx = __uint_as_float(hp << 16);
    float hy = __uint_as_float(hp & 0xffff0000u);
    return pack2bf(x - hx, y - hy);
}

// ---------------------------------------------------------------------------
// Split + pack inputs: fp32 [rows,1024] -> bf16 [rows,3072]
//   amode=1 (activations): [hi | lo | hi];  amode=0 (weights): [hi | hi | lo]
// ---------------------------------------------------------------------------
__global__ void split_pack(const float* __restrict__ src, int dst, int amode)
{
    __nv_bfloat16* out = (dst == 0) ? g_xp : (dst == 1) ? g_wqp : g_wpp;
    size_t idx = (size_t)blockIdx.x * 256 + threadIdx.x;
    size_t m = idx >> 8;
    int k = (int)(idx & 255) * 4;
    float4 v = *(const float4*)(src + m * DIM + k);
    uint32_t h0 = pack2bf(v.x, v.y), h1 = pack2bf(v.z, v.w);
    uint32_t l0 = packresid(h0, v.x, v.y), l1 = packresid(h1, v.z, v.w);
    __nv_bfloat16* o = out + m * KP + k;
    uint2 hi = make_uint2(h0, h1), lo = make_uint2(l0, l1);
    *(uint2*)(o) = hi;
    if (amode) { *(uint2*)(o + DIM) = lo; *(uint2*)(o + 2 * DIM) = hi; }
    else       { *(uint2*)(o + DIM) = hi; *(uint2*)(o + 2 * DIM) = lo; }
}

// ---------------------------------------------------------------------------
// bf16 HMMA GEMM: C[M,N] = A'[M,KP] * B'[N,KP]^T
// mode 0: qkv pass (A=g_xp, B=g_wqp) -> bf16 hi/lo Q/K/V buffers
// mode 1: proj pass (A=g_aop, B=g_wpp) -> fp32 Cout [M, 1024]
// ---------------------------------------------------------------------------
#define GSTAGE_BYTES 32768
#define GB_OFF 16384
#define GSMEM (3 * GSTAGE_BYTES)

__global__ __launch_bounds__(256, 2)
void gemm_bf16(int mode, float* __restrict__ Cout, int N)
{
    const __nv_bfloat16* A = mode ? g_aop : g_xp;
    const __nv_bfloat16* B = mode ? g_wpp : g_wqp;

    extern __shared__ char sm[];
    const uint32_t sb = smem_u32(sm);
    const int tid = threadIdx.x, lane = tid & 31, wid = tid >> 5;
    const int wm = wid >> 1, wn = wid & 1;
    const int bm = blockIdx.y * 128, bn = blockIdx.x * 128;

    const __nv_bfloat16* Ag = A + (size_t)bm * KP;
    const __nv_bfloat16* Bg = B + (size_t)bn * KP;

    const int ldrow = tid >> 1;
    const int ldc0 = (tid & 1) * 4;

    auto load_stage = [&](int ch, int s) {
        const size_t ko = (size_t)ch * 64;
        uint32_t base = sb + s * GSTAGE_BYTES;
        const __nv_bfloat16* a = Ag + (size_t)ldrow * KP + ko;
        const __nv_bfloat16* b = Bg + (size_t)ldrow * KP + ko;
        uint32_t rbase = base + ldrow * 128;
#pragma unroll
        for (int i = 0; i < 4; i++) {
            int c16 = ldc0 + i;
            uint32_t sw = rbase + (uint32_t)((c16 ^ (ldrow & 7)) << 4);
            CPA16(sw, a + c16 * 8);
            CPA16(sw + GB_OFF, b + c16 * 8);
        }
        CP_COMMIT();
    };

    load_stage(0, 0);
    load_stage(1, 1);

    float acc[2][8][4];
#pragma unroll
    for (int i = 0; i < 2; i++)
#pragma unroll
        for (int j = 0; j < 8; j++)
#pragma unroll
            for (int q = 0; q < 4; q++) acc[i][j][q] = 0.f;

    const int arow0 = wm * 32 + (lane & 15);
    const int alc = lane >> 4;
    const int brow0 = wn * 64 + ((lane >> 4) & 1) * 8 + (lane & 7);
    const int bc = (lane >> 3) & 1;

    for (int ch = 0; ch < NCH; ch++) {
        const int s = ch % 3;
        if (ch + 1 < NCH) { asm volatile("cp.async.wait_group 1;" ::: "memory"); }
        else              { asm volatile("cp.async.wait_group 0;" ::: "memory"); }
        __syncthreads();
        if (ch + 2 < NCH) load_stage(ch + 2, (ch + 2) % 3);

        const uint32_t Ab = sb + s * GSTAGE_BYTES;
        const uint32_t Bb = Ab + GB_OFF;
#pragma unroll
        for (int kk = 0; kk < 4; kk++) {
            uint32_t a0[4], a1[4];
            {
                int c = kk * 2 + alc;
                int r0 = arow0;
                ldsm4(a0, Ab + r0 * 128 + ((c ^ (r0 & 7)) << 4));
                int r1 = arow0 + 16;
                ldsm4(a1, Ab + r1 * 128 + ((c ^ (r1 & 7)) << 4));
            }
            // software-pipelined B fragments
            uint32_t bq[2][4];
            {
                int r = brow0, c = kk * 2 + bc;
                ldsm4(bq[0], Bb + r * 128 + ((c ^ (r & 7)) << 4));
            }
#pragma unroll
            for (int bp = 0; bp < 4; bp++) {
                if (bp < 3) {
                    int r = brow0 + (bp + 1) * 16, c = kk * 2 + bc;
                    ldsm4(bq[(bp + 1) & 1], Bb + r * 128 + ((c ^ (r & 7)) << 4));
                }
                const uint32_t* b = bq[bp & 1];
                mma_bf16(acc[0][2 * bp],     a0, b);
                mma_bf16(acc[0][2 * bp + 1], a0, b + 2);
                mma_bf16(acc[1][2 * bp],     a1, b);
                mma_bf16(acc[1][2 * bp + 1], a1, b + 2);
            }
        }
    }

    const int g = lane >> 2, t = lane & 3;
    if (mode) {
        // fp32 epilogue
#pragma unroll
        for (int mf = 0; mf < 2; mf++) {
            int row = bm + wm * 32 + mf * 16 + g;
#pragma unroll
            for (int nf = 0; nf < 8; nf++) {
                int col = bn + wn * 64 + nf * 8 + t * 2;
                *(float2*)(Cout + (size_t)row * N + col) =
                    make_float2(acc[mf][nf][0], acc[mf][nf][1]);
                *(float2*)(Cout + (size_t)(row + 8) * N + col) =
                    make_float2(acc[mf][nf][2], acc[mf][nf][3]);
            }
        }
    } else {
        // bf16 hi/lo epilogue into per-head Q/K/V
        int col0 = bn + wn * 64;
        int mat = col0 >> 10;
        int hh = (col0 & 1023) >> 6;
        __nv_bfloat16* BH = (mat == 0) ? g_qh : (mat == 1) ? g_kh : g_vh;
        __nv_bfloat16* BL = (mat == 0) ? g_ql : (mat == 1) ? g_kl : g_vl;
#pragma unroll
        for (int mf = 0; mf < 2; mf++) {
            int rg = bm + wm * 32 + mf * 16 + g;
            int bb = rg >> 11, l = rg & 2047;
            size_t base = ((size_t)(bb * NHEADS + hh) * SEQ + l) * HDIM;
#pragma unroll
            for (int nf = 0; nf < 8; nf++) {
                int d = nf * 8 + t * 2;
                float x0 = acc[mf][nf][0], x1 = acc[mf][nf][1];
                uint32_t h0 = pack2bf(x0, x1);
                *(uint32_t*)(BH + base + d) = h0;
                *(uint32_t*)(BL + base + d) = packresid(h0, x0, x1);
                float y0 = acc[mf][nf][2], y1 = acc[mf][nf][3];
                uint32_t h1 = pack2bf(y0, y1);
                *(uint32_t*)(BH + base + 8 * HDIM + d) = h1;
                *(uint32_t*)(BL + base + 8 * HDIM + d) = packresid(h1, y0, y1);
            }
        }
    }
}

// ---------------------------------------------------------------------------
// Flash attention, pure HMMA inner loop.
// CTA: 256 thr (8 warps), 128 q-rows; KV tile 64, cp.async double-buffered.
// Warp w owns q rows w*16..w*16+15. Q frags in regs.
// smem: 2 stages x 32KB (Khi|Klo|Vhi|Vlo, each 64x128B swizzled).
// ---------------------------------------------------------------------------
#define AT_SMEM 65536
#define NIT (SEQ / 64)

__global__ __launch_bounds__(256, 2)
void attn_tc()
{
    extern __shared__ char smem[];
    const uint32_t sb = smem_u32(smem);
    const int tid = threadIdx.x, lane = tid & 31, wid = tid >> 5;
    const int b = blockIdx.z, h = blockIdx.y, q0 = blockIdx.x * 128;
    const size_t bh = (size_t)(b * NHEADS + h) * SEQ;

    // ---- stage Q (128x64 hi/lo) through smem once ----
    {
        const __nv_bfloat16* srcs[2] = { g_qh + (bh + q0) * HDIM, g_ql + (bh + q0) * HDIM };
#pragma unroll
        for (int m = 0; m < 2; m++)
#pragma unroll
            for (int i = 0; i < 4; i++) {
                int idx = i * 256 + tid;           // 0..1023
                int row = idx >> 3, c16 = idx & 7;
                uint32_t sw = sb + m * 16384 + row * 128 + ((c16 ^ (row & 7)) << 4);
                CPA16(sw, srcs[m] + (size_t)row * HDIM + c16 * 8);
            }
        CP_COMMIT();
        asm volatile("cp.async.wait_group 0;" ::: "memory");
    }
    __syncthreads();

    uint32_t qh[4][4], ql[4][4];
    {
        int r = wid * 16 + (lane & 15);
        int cl = lane >> 4;
#pragma unroll
        for (int kk = 0; kk < 4; kk++) {
            uint32_t off = r * 128 + (((kk * 2 + cl) ^ (r & 7)) << 4);
            ldsm4(qh[kk], sb + off);
            ldsm4(ql[kk], sb + 16384 + off);
        }
    }
    __syncthreads();

    auto load_kv = [&](int it, int s) {
        const size_t rb = bh + (size_t)it * 64;
        const __nv_bfloat16* srcs[4] = { g_kh, g_kl, g_vh, g_vl };
        uint32_t dst = sb + s * 32768;
#pragma unroll
        for (int m = 0; m < 4; m++)
#pragma unroll
            for (int i = 0; i < 2; i++) {
                int idx = i * 256 + tid;           // 0..511
                int row = idx >> 3, c16 = idx & 7;
                uint32_t sw = dst + m * 8192 + row * 128 + ((c16 ^ (row & 7)) << 4);
                CPA16(sw, srcs[m] + (rb + row) * HDIM + c16 * 8);
            }
        CP_COMMIT();
    };

    load_kv(0, 0);

    float o[8][4];
#pragma unroll
    for (int i = 0; i < 8; i++)
#pragma unroll
        for (int j = 0; j < 4; j++) o[i][j] = 0.f;
    float m0 = -1e30f, m1 = -1e30f, l0s = 0.f, l1s = 0.f;

    const int brow0 = ((lane >> 4) & 1) * 8 + (lane & 7);
    const int bc = (lane >> 3) & 1;
    const int vlc = lane >> 4;

    for (int it = 0; it < NIT; it++) {
        const int s = it & 1;
        if (it + 1 < NIT) {
            load_kv(it + 1, (it + 1) & 1);
            asm volatile("cp.async.wait_group 1;" ::: "memory");
        } else {
            asm volatile("cp.async.wait_group 0;" ::: "memory");
        }
        __syncthreads();
        const uint32_t KH = sb + s * 32768;
        const uint32_t KL = KH + 8192;
        const uint32_t VH = KH + 16384;
        const uint32_t VL = KH + 24576;

        // ---- S = Q K^T ----
        float sx[8][4];
#pragma unroll
        for (int i = 0; i < 8; i++)
#pragma unroll
            for (int j = 0; j < 4; j++) sx[i][j] = 0.f;
#pragma unroll
        for (int kk = 0; kk < 4; kk++) {
#pragma unroll
            for (int bp = 0; bp < 4; bp++) {
                uint32_t bhf[4], blf[4];
                int r = brow0 + bp * 16;
                int c = kk * 2 + bc;
                uint32_t off = r * 128 + ((c ^ (r & 7)) << 4);
                ldsm4(bhf, KH + off);
                ldsm4(blf, KL + off);
                mma_bf16(sx[2 * bp],     qh[kk], bhf);
                mma_bf16(sx[2 * bp + 1], qh[kk], bhf + 2);
                mma_bf16(sx[2 * bp],     qh[kk], blf);
                mma_bf16(sx[2 * bp + 1], qh[kk], blf + 2);
                mma_bf16(sx[2 * bp],     ql[kk], bhf);
                mma_bf16(sx[2 * bp + 1], ql[kk], bhf + 2);
            }
        }

        // ---- online softmax ----
        float rmax0 = -1e30f, rmax1 = -1e30f;
#pragma unroll
        for (int nf = 0; nf < 8; nf++) {
            sx[nf][0] *= SM_SCALE; sx[nf][1] *= SM_SCALE;
            sx[nf][2] *= SM_SCALE; sx[nf][3] *= SM_SCALE;
            rmax0 = fmaxf(rmax0, fmaxf(sx[nf][0], sx[nf][1]));
            rmax1 = fmaxf(rmax1, fmaxf(sx[nf][2], sx[nf][3]));
        }
        rmax0 = fmaxf(rmax0, __shfl_xor_sync(0xffffffffu, rmax0, 1));
        rmax0 = fmaxf(rmax0, __shfl_xor_sync(0xffffffffu, rmax0, 2));
        rmax1 = fmaxf(rmax1, __shfl_xor_sync(0xffffffffu, rmax1, 1));
        rmax1 = fmaxf(rmax1, __shfl_xor_sync(0xffffffffu, rmax1, 2));
        float mn0 = fmaxf(m0, rmax0), mn1 = fmaxf(m1, rmax1);
        float corr0 = __expf(m0 - mn0), corr1 = __expf(m1 - mn1);
        float sum0 = 0.f, sum1 = 0.f;
#pragma unroll
        for (int nf = 0; nf < 8; nf++) {
            sx[nf][0] = __expf(sx[nf][0] - mn0);
            sx[nf][1] = __expf(sx[nf][1] - mn0);
            sx[nf][2] = __expf(sx[nf][2] - mn1);
            sx[nf][3] = __expf(sx[nf][3] - mn1);
            sum0 += sx[nf][0] + sx[nf][1];
            sum1 += sx[nf][2] + sx[nf][3];
        }
        sum0 += __shfl_xor_sync(0xffffffffu, sum0, 1);
        sum0 += __shfl_xor_sync(0xffffffffu, sum0, 2);
        sum1 += __shfl_xor_sync(0xffffffffu, sum1, 1);
        sum1 += __shfl_xor_sync(0xffffffffu, sum1, 2);
        l0s = l0s * corr0 + sum0;
        l1s = l1s * corr1 + sum1;
        m0 = mn0; m1 = mn1;
#pragma unroll
        for (int nf = 0; nf < 8; nf++) {
            o[nf][0] *= corr0; o[nf][1] *= corr0;
            o[nf][2] *= corr1; o[nf][3] *= corr1;
        }

        // ---- O += P V ----
#pragma unroll
        for (int kk = 0; kk < 4; kk++) {
            uint32_t ah[4], al[4];
            ah[0] = pack2bf(sx[2 * kk][0], sx[2 * kk][1]);
            ah[1] = pack2bf(sx[2 * kk][2], sx[2 * kk][3]);
            ah[2] = pack2bf(sx[2 * kk + 1][0], sx[2 * kk + 1][1]);
            ah[3] = pack2bf(sx[2 * kk + 1][2], sx[2 * kk + 1][3]);
            al[0] = packresid(ah[0], sx[2 * kk][0], sx[2 * kk][1]);
            al[1] = packresid(ah[1], sx[2 * kk][2], sx[2 * kk][3]);
            al[2] = packresid(ah[2], sx[2 * kk + 1][0], sx[2 * kk + 1][1]);
            al[3] = packresid(ah[3], sx[2 * kk + 1][2], sx[2 * kk + 1][3]);
#pragma unroll
            for (int hp = 0; hp < 4; hp++) {
                uint32_t vh[4], vl[4];
                int r = kk * 16 + ((lane >> 3) & 1) * 8 + (lane & 7);
                int c = hp * 2 + vlc;
                uint32_t off = r * 128 + ((c ^ (r & 7)) << 4);
                ldsm4t(vh, VH + off);
                ldsm4t(vl, VL + off);
                mma_bf16(o[2 * hp],     ah, vh);
                mma_bf16(o[2 * hp + 1], ah, vh + 2);
                mma_bf16(o[2 * hp],     ah, vl);
                mma_bf16(o[2 * hp + 1], ah, vl + 2);
                mma_bf16(o[2 * hp],     al, vh);
                mma_bf16(o[2 * hp + 1], al, vh + 2);
            }
        }
        __syncthreads();
    }

    // ---- epilogue: write packed (hi|lo|hi) proj operand ----
    const int g = lane >> 2, t = lane & 3;
    float inv0 = 1.f / l0s, inv1 = 1.f / l1s;
    size_t arow0 = (size_t)b * SEQ + q0 + wid * 16 + g;
#pragma unroll
    for (int nf = 0; nf < 8; nf++) {
        int col = h * 64 + nf * 8 + t * 2;
        {
            float x0 = o[nf][0] * inv0, x1 = o[nf][1] * inv0;
            uint32_t hv = pack2bf(x0, x1);
            uint32_t lv = packresid(hv, x0, x1);
            __nv_bfloat16* p = g_aop + arow0 * KP + col;
            *(uint32_t*)(p) = hv;
            *(uint32_t*)(p + DIM) = lv;
            *(uint32_t*)(p + 2 * DIM) = hv;
        }
        {
            float x0 = o[nf][2] * inv1, x1 = o[nf][3] * inv1;
            uint32_t hv = pack2bf(x0, x1);
            uint32_t lv = packresid(hv, x0, x1);
            __nv_bfloat16* p = g_aop + (arow0 + 8) * KP + col;
            *(uint32_t*)(p) = hv;
            *(uint32_t*)(p + DIM) = lv;
            *(uint32_t*)(p + 2 * DIM) = hv;
        }
    }
}

// ---------------------------------------------------------------------------
// Launch
// ---------------------------------------------------------------------------
extern "C" void kernel_launch(void* const* d_in, const int* in_sizes, int n_in,
                              void* d_out, int out_size)
{
    const float* x      = (const float*)d_in[0];
    const float* w_qkv  = (const float*)d_in[1];
    const float* w_proj = (const float*)d_in[2];
    float* out = (float*)d_out;
    (void)in_sizes; (void)n_in; (void)out_size;

    cudaFuncSetAttribute(gemm_bf16, cudaFuncAttributeMaxDynamicSharedMemorySize, GSMEM);
    cudaFuncSetAttribute(attn_tc, cudaFuncAttributeMaxDynamicSharedMemorySize, AT_SMEM);

    // input splits
    split_pack<<<MROWS, 256>>>(x, 0, 1);
    split_pack<<<3 * DIM, 256>>>(w_qkv, 1, 0);
    split_pack<<<DIM, 256>>>(w_proj, 2, 0);

    // QKV projection + fused bf16 hi/lo epilogue
    gemm_bf16<<<dim3(3 * DIM / 128, MROWS / 128), 256, GSMEM>>>(0, nullptr, 3 * DIM);

    // attention (writes packed proj operand)
    attn_tc<<<dim3(SEQ / 128, NHEADS, BATCH), 256, AT_SMEM>>>();

    // output projection
    gemm_bf16<<<dim3(DIM / 128, MROWS / 128), 256, GSMEM>>>(1, out, DIM);
}

// round 5
// speedup vs baseline: 1.0587x; 1.0587x over previous
#include <cuda_runtime.h>
#include <cuda_bf16.h>
#include <cstdint>

#define BATCH 2
#define SEQ 2048
#define DIM 1024
#define NHEADS 16
#define HDIM 64
#define SM_SCALE 0.125f
#define QSCALE 0.1803368801111204f   // SM_SCALE * log2(e)
#define MROWS 4096
#define KP 3072
#define NCH 48

// ---------------------------------------------------------------------------
// Scratch (device globals: allocation-free)
// ---------------------------------------------------------------------------
__device__ __align__(16) __nv_bfloat16 g_xp [(size_t)MROWS * KP];
__device__ __align__(16) __nv_bfloat16 g_wqp[(size_t)3 * DIM * KP];
__device__ __align__(16) __nv_bfloat16 g_wpp[(size_t)DIM * KP];
__device__ __align__(16) __nv_bfloat16 g_aop[(size_t)MROWS * KP];

#define QKV_ELEMS ((size_t)BATCH * NHEADS * SEQ * HDIM)
__device__ __align__(16) __nv_bfloat16 g_qh[QKV_ELEMS];
__device__ __align__(16) __nv_bfloat16 g_ql[QKV_ELEMS];
__device__ __align__(16) __nv_bfloat16 g_kh[QKV_ELEMS];
__device__ __align__(16) __nv_bfloat16 g_kl[QKV_ELEMS];
__device__ __align__(16) __nv_bfloat16 g_vh[QKV_ELEMS];
__device__ __align__(16) __nv_bfloat16 g_vl[QKV_ELEMS];

// ---------------------------------------------------------------------------
// Base-ISA helpers
// ---------------------------------------------------------------------------
__device__ __forceinline__ uint32_t smem_u32(const void* p) {
    uint32_t a;
    asm("{ .reg .u64 t; cvta.to.shared.u64 t, %1; cvt.u32.u64 %0, t; }"
        : "=r"(a) : "l"(p));
    return a;
}
__device__ __forceinline__ void ldsm4(uint32_t* r, uint32_t a) {
    asm volatile("ldmatrix.sync.aligned.m8n8.x4.shared.b16 {%0,%1,%2,%3}, [%4];"
        : "=r"(r[0]), "=r"(r[1]), "=r"(r[2]), "=r"(r[3]) : "r"(a));
}
__device__ __forceinline__ void ldsm4t(uint32_t* r, uint32_t a) {
    asm volatile("ldmatrix.sync.aligned.m8n8.x4.trans.shared.b16 {%0,%1,%2,%3}, [%4];"
        : "=r"(r[0]), "=r"(r[1]), "=r"(r[2]), "=r"(r[3]) : "r"(a));
}
__device__ __forceinline__ void mma_bf16(float* c, const uint32_t* a, const uint32_t* b) {
    asm volatile(
        "mma.sync.aligned.m16n8k16.row.col.f32.bf16.bf16.f32 "
        "{%0,%1,%2,%3}, {%4,%5,%6,%7}, {%8,%9}, {%0,%1,%2,%3};"
        : "+f"(c[0]), "+f"(c[1]), "+f"(c[2]), "+f"(c[3])
        : "r"(a[0]), "r"(a[1]), "r"(a[2]), "r"(a[3]), "r"(b[0]), "r"(b[1]));
}
#define CPA16(d, s) \
    asm volatile("cp.async.cg.shared.global [%0], [%1], 16;" :: "r"(d), "l"(s))
#define CP_COMMIT() asm volatile("cp.async.commit_group;" ::: "memory")

__device__ __forceinline__ float ex2(float x) {
    float r; asm("ex2.approx.f32 %0, %1;" : "=f"(r) : "f"(x)); return r;
}
__device__ __forceinline__ uint32_t pack2bf(float x, float y) {
    __nv_bfloat162 t = __float22bfloat162_rn(make_float2(x, y));
    return *reinterpret_cast<uint32_t*>(&t);
}
__device__ __forceinline__ uint32_t packresid(uint32_t hp, float x, float y) {
    float hx = __uint_as_float(hp << 16);
    float hy = __uint_as_float(hp & 0xffff0000u);
    return pack2bf(x - hx, y - hy);
}

// ---------------------------------------------------------------------------
// Split + pack inputs
// ---------------------------------------------------------------------------
__global__ void split_pack(const float* __restrict__ src, int dst, int amode)
{
    __nv_bfloat16* out = (dst == 0) ? g_xp : (dst == 1) ? g_wqp : g_wpp;
    size_t idx = (size_t)blockIdx.x * 256 + threadIdx.x;
    size_t m = idx >> 8;
    int k = (int)(idx & 255) * 4;
    float4 v = *(const float4*)(src + m * DIM + k);
    uint32_t h0 = pack2bf(v.x, v.y), h1 = pack2bf(v.z, v.w);
    uint32_t l0 = packresid(h0, v.x, v.y), l1 = packresid(h1, v.z, v.w);
    __nv_bfloat16* o = out + m * KP + k;
    uint2 hi = make_uint2(h0, h1), lo = make_uint2(l0, l1);
    *(uint2*)(o) = hi;
    if (amode) { *(uint2*)(o + DIM) = lo; *(uint2*)(o + 2 * DIM) = hi; }
    else       { *(uint2*)(o + DIM) = hi; *(uint2*)(o + 2 * DIM) = lo; }
}

// ---------------------------------------------------------------------------
// bf16 HMMA GEMM (R3 inner loop + fused bf16 epilogue for mode 0)
// ---------------------------------------------------------------------------
#define GSTAGE_BYTES 32768
#define GB_OFF 16384
#define GSMEM (3 * GSTAGE_BYTES)

__global__ __launch_bounds__(256, 2)
void gemm_bf16(int mode, float* __restrict__ Cout, int N)
{
    const __nv_bfloat16* A = mode ? g_aop : g_xp;
    const __nv_bfloat16* B = mode ? g_wpp : g_wqp;

    extern __shared__ char sm[];
    const uint32_t sb = smem_u32(sm);
    const int tid = threadIdx.x, lane = tid & 31, wid = tid >> 5;
    const int wm = wid >> 1, wn = wid & 1;
    const int bm = blockIdx.y * 128, bn = blockIdx.x * 128;

    const __nv_bfloat16* Ag = A + (size_t)bm * KP;
    const __nv_bfloat16* Bg = B + (size_t)bn * KP;

    const int ldrow = tid >> 1;
    const int ldc0 = (tid & 1) * 4;

    auto load_stage = [&](int ch, int s) {
        const size_t ko = (size_t)ch * 64;
        uint32_t base = sb + s * GSTAGE_BYTES;
        const __nv_bfloat16* a = Ag + (size_t)ldrow * KP + ko;
        const __nv_bfloat16* b = Bg + (size_t)ldrow * KP + ko;
        uint32_t rbase = base + ldrow * 128;
#pragma unroll
        for (int i = 0; i < 4; i++) {
            int c16 = ldc0 + i;
            uint32_t sw = rbase + (uint32_t)((c16 ^ (ldrow & 7)) << 4);
            CPA16(sw, a + c16 * 8);
            CPA16(sw + GB_OFF, b + c16 * 8);
        }
        CP_COMMIT();
    };

    load_stage(0, 0);
    load_stage(1, 1);

    float acc[2][8][4];
#pragma unroll
    for (int i = 0; i < 2; i++)
#pragma unroll
        for (int j = 0; j < 8; j++)
#pragma unroll
            for (int q = 0; q < 4; q++) acc[i][j][q] = 0.f;

    const int arow0 = wm * 32 + (lane & 15);
    const int alc = lane >> 4;
    const int brow0 = wn * 64 + ((lane >> 4) & 1) * 8 + (lane & 7);
    const int bc = (lane >> 3) & 1;

    for (int ch = 0; ch < NCH; ch++) {
        const int s = ch % 3;
        if (ch + 1 < NCH) { asm volatile("cp.async.wait_group 1;" ::: "memory"); }
        else              { asm volatile("cp.async.wait_group 0;" ::: "memory"); }
        __syncthreads();
        const uint32_t Ab = sb + s * GSTAGE_BYTES;
        const uint32_t Bb = Ab + GB_OFF;
#pragma unroll
        for (int kk = 0; kk < 4; kk++) {
            uint32_t a0[4], a1[4];
            {
                int c = kk * 2 + alc;
                int r0 = arow0;
                ldsm4(a0, Ab + r0 * 128 + ((c ^ (r0 & 7)) << 4));
                int r1 = arow0 + 16;
                ldsm4(a1, Ab + r1 * 128 + ((c ^ (r1 & 7)) << 4));
            }
#pragma unroll
            for (int bp = 0; bp < 4; bp++) {
                uint32_t b[4];
                int r = brow0 + bp * 16;
                int c = kk * 2 + bc;
                ldsm4(b, Bb + r * 128 + ((c ^ (r & 7)) << 4));
                mma_bf16(acc[0][2 * bp],     a0, b);
                mma_bf16(acc[0][2 * bp + 1], a0, b + 2);
                mma_bf16(acc[1][2 * bp],     a1, b);
                mma_bf16(acc[1][2 * bp + 1], a1, b + 2);
            }
        }
        if (ch + 2 < NCH) load_stage(ch + 2, (ch + 2) % 3);
    }

    const int g = lane >> 2, t = lane & 3;
    if (mode) {
#pragma unroll
        for (int mf = 0; mf < 2; mf++) {
            int row = bm + wm * 32 + mf * 16 + g;
#pragma unroll
            for (int nf = 0; nf < 8; nf++) {
                int col = bn + wn * 64 + nf * 8 + t * 2;
                *(float2*)(Cout + (size_t)row * N + col) =
                    make_float2(acc[mf][nf][0], acc[mf][nf][1]);
                *(float2*)(Cout + (size_t)(row + 8) * N + col) =
                    make_float2(acc[mf][nf][2], acc[mf][nf][3]);
            }
        }
    } else {
        int col0 = bn + wn * 64;
        int mat = col0 >> 10;
        int hh = (col0 & 1023) >> 6;
        __nv_bfloat16* BH = (mat == 0) ? g_qh : (mat == 1) ? g_kh : g_vh;
        __nv_bfloat16* BL = (mat == 0) ? g_ql : (mat == 1) ? g_kl : g_vl;
#pragma unroll
        for (int mf = 0; mf < 2; mf++) {
            int rg = bm + wm * 32 + mf * 16 + g;
            int bb = rg >> 11, l = rg & 2047;
            size_t base = ((size_t)(bb * NHEADS + hh) * SEQ + l) * HDIM;
#pragma unroll
            for (int nf = 0; nf < 8; nf++) {
                int d = nf * 8 + t * 2;
                float x0 = acc[mf][nf][0], x1 = acc[mf][nf][1];
                uint32_t h0 = pack2bf(x0, x1);
                *(uint32_t*)(BH + base + d) = h0;
                *(uint32_t*)(BL + base + d) = packresid(h0, x0, x1);
                float y0 = acc[mf][nf][2], y1 = acc[mf][nf][3];
                uint32_t h1 = pack2bf(y0, y1);
                *(uint32_t*)(BH + base + 8 * HDIM + d) = h1;
                *(uint32_t*)(BL + base + 8 * HDIM + d) = packresid(h1, y0, y1);
            }
        }
    }
}

// ---------------------------------------------------------------------------
// Flash attention: 3-stage KV ring, one barrier per tile, exp2 softmax.
// CTA 256 thr, 128 q rows; KV tile 64.
// smem: 3 x 32KB stages (Khi|Klo|Vhi|Vlo @ 8KB each). Q staged via slot 2.
// ---------------------------------------------------------------------------
#define AT_SMEM 98304
#define NIT (SEQ / 64)

__global__ __launch_bounds__(256, 2)
void attn_tc()
{
    extern __shared__ char smem[];
    const uint32_t sb = smem_u32(smem);
    const int tid = threadIdx.x, lane = tid & 31, wid = tid >> 5;
    const int b = blockIdx.z, h = blockIdx.y, q0 = blockIdx.x * 128;
    const size_t bh = (size_t)(b * NHEADS + h) * SEQ;

    // ---- stage Q (128x64 hi/lo) via slot-2 smem ----
    {
        const uint32_t qbase = sb + 2 * 32768;
        const __nv_bfloat16* srcs[2] = { g_qh + (bh + q0) * HDIM, g_ql + (bh + q0) * HDIM };
#pragma unroll
        for (int m = 0; m < 2; m++)
#pragma unroll
            for (int i = 0; i < 4; i++) {
                int idx = i * 256 + tid;
                int row = idx >> 3, c16 = idx & 7;
                uint32_t sw = qbase + m * 16384 + row * 128 + ((c16 ^ (row & 7)) << 4);
                CPA16(sw, srcs[m] + (size_t)row * HDIM + c16 * 8);
            }
        CP_COMMIT();
        asm volatile("cp.async.wait_group 0;" ::: "memory");
    }
    __syncthreads();

    uint32_t qh[4][4], ql[4][4];
    {
        const uint32_t qbase = sb + 2 * 32768;
        int r = wid * 16 + (lane & 15);
        int cl = lane >> 4;
#pragma unroll
        for (int kk = 0; kk < 4; kk++) {
            uint32_t off = r * 128 + (((kk * 2 + cl) ^ (r & 7)) << 4);
            ldsm4(qh[kk], qbase + off);
            ldsm4(ql[kk], qbase + 16384 + off);
        }
    }
    __syncthreads();

    auto load_kv = [&](int it, int s) {
        const size_t rb = bh + (size_t)it * 64;
        const __nv_bfloat16* srcs[4] = { g_kh, g_kl, g_vh, g_vl };
        uint32_t dst = sb + s * 32768;
#pragma unroll
        for (int m = 0; m < 4; m++)
#pragma unroll
            for (int i = 0; i < 2; i++) {
                int idx = i * 256 + tid;
                int row = idx >> 3, c16 = idx & 7;
                uint32_t sw = dst + m * 8192 + row * 128 + ((c16 ^ (row & 7)) << 4);
                CPA16(sw, srcs[m] + (rb + row) * HDIM + c16 * 8);
            }
        CP_COMMIT();
    };

    load_kv(0, 0);
    load_kv(1, 1);

    float o[8][4];
#pragma unroll
    for (int i = 0; i < 8; i++)
#pragma unroll
        for (int j = 0; j < 4; j++) o[i][j] = 0.f;
    float m0 = -1e30f, m1 = -1e30f, l0s = 0.f, l1s = 0.f;

    const int brow0 = ((lane >> 4) & 1) * 8 + (lane & 7);
    const int bc = (lane >> 3) & 1;
    const int vlc = lane >> 4;

    for (int it = 0; it < NIT; it++) {
        const int s = it % 3;
        if (it + 1 < NIT) { asm volatile("cp.async.wait_group 1;" ::: "memory"); }
        else              { asm volatile("cp.async.wait_group 0;" ::: "memory"); }
        __syncthreads();                       // all warps done with it-1
        if (it + 2 < NIT) load_kv(it + 2, (it + 2) % 3);

        const uint32_t KH = sb + s * 32768;
        const uint32_t KL = KH + 8192;
        const uint32_t VH = KH + 16384;
        const uint32_t VL = KH + 24576;

        // ---- S = Q K^T ----
        float sx[8][4];
#pragma unroll
        for (int i = 0; i < 8; i++)
#pragma unroll
            for (int j = 0; j < 4; j++) sx[i][j] = 0.f;
#pragma unroll
        for (int kk = 0; kk < 4; kk++) {
#pragma unroll
            for (int bp = 0; bp < 4; bp++) {
                uint32_t bhf[4], blf[4];
                int r = brow0 + bp * 16;
                int c = kk * 2 + bc;
                uint32_t off = r * 128 + ((c ^ (r & 7)) << 4);
                ldsm4(bhf, KH + off);
                ldsm4(blf, KL + off);
                mma_bf16(sx[2 * bp],     qh[kk], bhf);
                mma_bf16(sx[2 * bp + 1], qh[kk], bhf + 2);
                mma_bf16(sx[2 * bp],     qh[kk], blf);
                mma_bf16(sx[2 * bp + 1], qh[kk], blf + 2);
                mma_bf16(sx[2 * bp],     ql[kk], bhf);
                mma_bf16(sx[2 * bp + 1], ql[kk], bhf + 2);
            }
        }

        // ---- online softmax (exp2 domain) ----
        float rmax0 = -1e30f, rmax1 = -1e30f;
#pragma unroll
        for (int nf = 0; nf < 8; nf++) {
            sx[nf][0] *= QSCALE; sx[nf][1] *= QSCALE;
            sx[nf][2] *= QSCALE; sx[nf][3] *= QSCALE;
            rmax0 = fmaxf(rmax0, fmaxf(sx[nf][0], sx[nf][1]));
            rmax1 = fmaxf(rmax1, fmaxf(sx[nf][2], sx[nf][3]));
        }
        rmax0 = fmaxf(rmax0, __shfl_xor_sync(0xffffffffu, rmax0, 1));
        rmax0 = fmaxf(rmax0, __shfl_xor_sync(0xffffffffu, rmax0, 2));
        rmax1 = fmaxf(rmax1, __shfl_xor_sync(0xffffffffu, rmax1, 1));
        rmax1 = fmaxf(rmax1, __shfl_xor_sync(0xffffffffu, rmax1, 2));
        float mn0 = fmaxf(m0, rmax0), mn1 = fmaxf(m1, rmax1);
        float corr0 = ex2(m0 - mn0), corr1 = ex2(m1 - mn1);
        float sum0 = 0.f, sum1 = 0.f;
#pragma unroll
        for (int nf = 0; nf < 8; nf++) {
            sx[nf][0] = ex2(sx[nf][0] - mn0);
            sx[nf][1] = ex2(sx[nf][1] - mn0);
            sx[nf][2] = ex2(sx[nf][2] - mn1);
            sx[nf][3] = ex2(sx[nf][3] - mn1);
            sum0 += sx[nf][0] + sx[nf][1];
            sum1 += sx[nf][2] + sx[nf][3];
        }
        sum0 += __shfl_xor_sync(0xffffffffu, sum0, 1);
        sum0 += __shfl_xor_sync(0xffffffffu, sum0, 2);
        sum1 += __shfl_xor_sync(0xffffffffu, sum1, 1);
        sum1 += __shfl_xor_sync(0xffffffffu, sum1, 2);
        l0s = l0s * corr0 + sum0;
        l1s = l1s * corr1 + sum1;
        m0 = mn0; m1 = mn1;
#pragma unroll
        for (int nf = 0; nf < 8; nf++) {
            o[nf][0] *= corr0; o[nf][1] *= corr0;
            o[nf][2] *= corr1; o[nf][3] *= corr1;
        }

        // ---- O += P V ----
#pragma unroll
        for (int kk = 0; kk < 4; kk++) {
            uint32_t ah[4], al[4];
            ah[0] = pack2bf(sx[2 * kk][0], sx[2 * kk][1]);
            ah[1] = pack2bf(sx[2 * kk][2], sx[2 * kk][3]);
            ah[2] = pack2bf(sx[2 * kk + 1][0], sx[2 * kk + 1][1]);
            ah[3] = pack2bf(sx[2 * kk + 1][2], sx[2 * kk + 1][3]);
            al[0] = packresid(ah[0], sx[2 * kk][0], sx[2 * kk][1]);
            al[1] = packresid(ah[1], sx[2 * kk][2], sx[2 * kk][3]);
            al[2] = packresid(ah[2], sx[2 * kk + 1][0], sx[2 * kk + 1][1]);
            al[3] = packresid(ah[3], sx[2 * kk + 1][2], sx[2 * kk + 1][3]);
#pragma unroll
            for (int hp = 0; hp < 4; hp++) {
                uint32_t vh[4], vl[4];
                int r = kk * 16 + ((lane >> 3) & 1) * 8 + (lane & 7);
                int c = hp * 2 + vlc;
                uint32_t off = r * 128 + ((c ^ (r & 7)) << 4);
                ldsm4t(vh, VH + off);
                ldsm4t(vl, VL + off);
                mma_bf16(o[2 * hp],     ah, vh);
                mma_bf16(o[2 * hp + 1], ah, vh + 2);
                mma_bf16(o[2 * hp],     ah, vl);
                mma_bf16(o[2 * hp + 1], ah, vl + 2);
                mma_bf16(o[2 * hp],     al, vh);
                mma_bf16(o[2 * hp + 1], al, vh + 2);
            }
        }
    }

    // ---- epilogue: packed (hi|lo|hi) proj operand ----
    const int g = lane >> 2, t = lane & 3;
    float inv0 = 1.f / l0s, inv1 = 1.f / l1s;
    size_t arow0 = (size_t)b * SEQ + q0 + wid * 16 + g;
#pragma unroll
    for (int nf = 0; nf < 8; nf++) {
        int col = h * 64 + nf * 8 + t * 2;
        {
            float x0 = o[nf][0] * inv0, x1 = o[nf][1] * inv0;
            uint32_t hv = pack2bf(x0, x1);
            uint32_t lv = packresid(hv, x0, x1);
            __nv_bfloat16* p = g_aop + arow0 * KP + col;
            *(uint32_t*)(p) = hv;
            *(uint32_t*)(p + DIM) = lv;
            *(uint32_t*)(p + 2 * DIM) = hv;
        }
        {
            float x0 = o[nf][2] * inv1, x1 = o[nf][3] * inv1;
            uint32_t hv = pack2bf(x0, x1);
            uint32_t lv = packresid(hv, x0, x1);
            __nv_bfloat16* p = g_aop + (arow0 + 8) * KP + col;
            *(uint32_t*)(p) = hv;
            *(uint32_t*)(p + DIM) = lv;
            *(uint32_t*)(p + 2 * DIM) = hv;
        }
    }
}

// ---------------------------------------------------------------------------
// Launch
// ---------------------------------------------------------------------------
extern "C" void kernel_launch(void* const* d_in, const int* in_sizes, int n_in,
                              void* d_out, int out_size)
{
    const float* x      = (const float*)d_in[0];
    const float* w_qkv  = (const float*)d_in[1];
    const float* w_proj = (const float*)d_in[2];
    float* out = (float*)d_out;
    (void)in_sizes; (void)n_in; (void)out_size;

    cudaFuncSetAttribute(gemm_bf16, cudaFuncAttributeMaxDynamicSharedMemorySize, GSMEM);
    cudaFuncSetAttribute(attn_tc, cudaFuncAttributeMaxDynamicSharedMemorySize, AT_SMEM);

    split_pack<<<MROWS, 256>>>(x, 0, 1);
    split_pack<<<3 * DIM, 256>>>(w_qkv, 1, 0);
    split_pack<<<DIM, 256>>>(w_proj, 2, 0);

    gemm_bf16<<<dim3(3 * DIM / 128, MROWS / 128), 256, GSMEM>>>(0, nullptr, 3 * DIM);

    attn_tc<<<dim3(SEQ / 128, NHEADS, BATCH), 256, AT_SMEM>>>();

    gemm_bf16<<<dim3(DIM / 128, MROWS / 128), 256, GSMEM>>>(1, out, DIM);
}

// round 9
// speedup vs baseline: 1.8386x; 1.7366x over previous
#include <cuda_runtime.h>
#include <cuda_fp16.h>
#include <cstdint>

#define BATCH 2
#define SEQ 2048
#define DIM 1024
#define NHEADS 16
#define HDIM 64
#define QSCALE 0.1803368801111204f   // (1/8) * log2(e)
#define MROWS 4096
#define KP 2048                      // packed K' = 2*DIM (hi|lo)

// ---------------------------------------------------------------------------
// Scratch (device globals: allocation-free)
// ---------------------------------------------------------------------------
__device__ __align__(16) __half g_xp [(size_t)MROWS * KP];      // x   [xh|xl]
__device__ __align__(16) __half g_wqh[(size_t)3 * DIM * DIM];   // w_qkv hi
__device__ __align__(16) __half g_wph[(size_t)DIM * DIM];       // w_proj hi
__device__ __align__(16) __half g_aop[(size_t)MROWS * KP];      // attn out [h|l]

// per-head Q/K/V fp16, layout [b][h][l][64]
#define QKV_ELEMS ((size_t)BATCH * NHEADS * SEQ * HDIM)
__device__ __align__(16) __half g_q[QKV_ELEMS];
__device__ __align__(16) __half g_k[QKV_ELEMS];
__device__ __align__(16) __half g_v[QKV_ELEMS];

// ---------------------------------------------------------------------------
// Base-ISA helpers
// ---------------------------------------------------------------------------
__device__ __forceinline__ uint32_t smem_u32(const void* p) {
    uint32_t a;
    asm("{ .reg .u64 t; cvta.to.shared.u64 t, %1; cvt.u32.u64 %0, t; }"
        : "=r"(a) : "l"(p));
    return a;
}
__device__ __forceinline__ void ldsm4(uint32_t* r, uint32_t a) {
    asm volatile("ldmatrix.sync.aligned.m8n8.x4.shared.b16 {%0,%1,%2,%3}, [%4];"
        : "=r"(r[0]), "=r"(r[1]), "=r"(r[2]), "=r"(r[3]) : "r"(a));
}
__device__ __forceinline__ void ldsm4t(uint32_t* r, uint32_t a) {
    asm volatile("ldmatrix.sync.aligned.m8n8.x4.trans.shared.b16 {%0,%1,%2,%3}, [%4];"
        : "=r"(r[0]), "=r"(r[1]), "=r"(r[2]), "=r"(r[3]) : "r"(a));
}
__device__ __forceinline__ void mma_f16(float* c, const uint32_t* a, const uint32_t* b) {
    asm volatile(
        "mma.sync.aligned.m16n8k16.row.col.f32.f16.f16.f32 "
        "{%0,%1,%2,%3}, {%4,%5,%6,%7}, {%8,%9}, {%0,%1,%2,%3};"
        : "+f"(c[0]), "+f"(c[1]), "+f"(c[2]), "+f"(c[3])
        : "r"(a[0]), "r"(a[1]), "r"(a[2]), "r"(a[3]), "r"(b[0]), "r"(b[1]));
}
#define CPA16(d, s) \
    asm volatile("cp.async.cg.shared.global [%0], [%1], 16;" :: "r"(d), "l"(s))
#define CP_COMMIT() asm volatile("cp.async.commit_group;" ::: "memory")

__device__ __forceinline__ float ex2(float x) {
    float r; asm("ex2.approx.f32 %0, %1;" : "=f"(r) : "f"(x)); return r;
}
__device__ __forceinline__ uint32_t pack2h(float x, float y) {
    __half2 t = __floats2half2_rn(x, y);
    return *reinterpret_cast<uint32_t*>(&t);
}
// fp16 residual pack given the hi pack
__device__ __forceinline__ uint32_t packresid_h(uint32_t hp, float x, float y) {
    float hx = __half2float(__ushort_as_half((uint16_t)(hp & 0xffff)));
    float hy = __half2float(__ushort_as_half((uint16_t)(hp >> 16)));
    return pack2h(x - hx, y - hy);
}

// ---------------------------------------------------------------------------
// Splits
// ---------------------------------------------------------------------------
// x fp32 [M,1024] -> g_xp fp16 [M, 2048] = [hi | lo]
__global__ void split_x(const float* __restrict__ src)
{
    size_t idx = (size_t)blockIdx.x * 256 + threadIdx.x;
    size_t m = idx >> 8;
    int k = (int)(idx & 255) * 4;
    float4 v = *(const float4*)(src + m * DIM + k);
    uint32_t h0 = pack2h(v.x, v.y), h1 = pack2h(v.z, v.w);
    uint32_t l0 = packresid_h(h0, v.x, v.y), l1 = packresid_h(h1, v.z, v.w);
    *(uint2*)(g_xp + m * KP + k)       = make_uint2(h0, h1);
    *(uint2*)(g_xp + m * KP + DIM + k) = make_uint2(l0, l1);
}
// weights fp32 [N,1024] -> fp16 hi only
__global__ void split_w(const float* __restrict__ src, int dst)
{
    __half* out = dst ? g_wph : g_wqh;
    size_t idx = (size_t)blockIdx.x * 256 + threadIdx.x;
    size_t m = idx >> 8;
    int k = (int)(idx & 255) * 4;
    float4 v = *(const float4*)(src + m * DIM + k);
    *(uint2*)(out + m * DIM + k) = make_uint2(pack2h(v.x, v.y), pack2h(v.z, v.w));
}

// ---------------------------------------------------------------------------
// fp16 HMMA GEMM: C[M,N] = (Ah+Al)[M,K] * Bh[N,K]^T
// A packed [M,2048] (hi then lo per row); B [N,1024], re-read per phase.
// 32 chunks of 128 B: ch 0..15 = hi phase, 16..31 = lo phase (B chunk = ch&15).
// CTA 128x128, warp 32x64, 3-stage cp.async (R3/R5 proven loop).
// ---------------------------------------------------------------------------
#define GST 32768
#define GBOFF 16384
#define GSMEM (3 * GST)
#define NCHT 32

__global__ __launch_bounds__(256, 2)
void gemm_f16k(int mode, float* __restrict__ Cout, int N)
{
    const __half* A = mode ? g_aop : g_xp;
    const __half* B = mode ? g_wph : g_wqh;

    extern __shared__ char sm[];
    const uint32_t sb = smem_u32(sm);
    const int tid = threadIdx.x, lane = tid & 31, wid = tid >> 5;
    const int wm = wid >> 1, wn = wid & 1;
    const int bm = blockIdx.y * 128, bn = blockIdx.x * 128;

    const int ldrow = tid >> 1;
    const int ldc0 = (tid & 1) * 4;

    auto load_stage = [&](int ch, int s) {
        const __half* a = A + (size_t)(bm + ldrow) * KP + ch * 64;
        const __half* b = B + (size_t)(bn + ldrow) * DIM + (ch & 15) * 64;
        uint32_t rbase = sb + s * GST + ldrow * 128;
#pragma unroll
        for (int i = 0; i < 4; i++) {
            int c16 = ldc0 + i;
            uint32_t sw = rbase + (uint32_t)((c16 ^ (ldrow & 7)) << 4);
            CPA16(sw, a + c16 * 8);
            CPA16(sw + GBOFF, b + c16 * 8);
        }
        CP_COMMIT();
    };

    load_stage(0, 0);
    load_stage(1, 1);

    float acc[2][8][4];
#pragma unroll
    for (int i = 0; i < 2; i++)
#pragma unroll
        for (int j = 0; j < 8; j++)
#pragma unroll
            for (int q = 0; q < 4; q++) acc[i][j][q] = 0.f;

    const int arow0 = wm * 32 + (lane & 15);
    const int alc = lane >> 4;
    const int brow0 = wn * 64 + ((lane >> 4) & 1) * 8 + (lane & 7);
    const int bc = (lane >> 3) & 1;

    for (int ch = 0; ch < NCHT; ch++) {
        const int s = ch % 3;
        if (ch + 1 < NCHT) { asm volatile("cp.async.wait_group 1;" ::: "memory"); }
        else               { asm volatile("cp.async.wait_group 0;" ::: "memory"); }
        __syncthreads();
        const uint32_t Ab = sb + s * GST;
        const uint32_t Bb = Ab + GBOFF;
#pragma unroll
        for (int kk = 0; kk < 4; kk++) {
            uint32_t a0[4], a1[4];
            {
                int c = kk * 2 + alc;
                int r0 = arow0;
                ldsm4(a0, Ab + r0 * 128 + ((c ^ (r0 & 7)) << 4));
                int r1 = arow0 + 16;
                ldsm4(a1, Ab + r1 * 128 + ((c ^ (r1 & 7)) << 4));
            }
#pragma unroll
            for (int bp = 0; bp < 4; bp++) {
                uint32_t b[4];
                int r = brow0 + bp * 16;
                int c = kk * 2 + bc;
                ldsm4(b, Bb + r * 128 + ((c ^ (r & 7)) << 4));
                mma_f16(acc[0][2 * bp],     a0, b);
                mma_f16(acc[0][2 * bp + 1], a0, b + 2);
                mma_f16(acc[1][2 * bp],     a1, b);
                mma_f16(acc[1][2 * bp + 1], a1, b + 2);
            }
        }
        if (ch + 2 < NCHT) load_stage(ch + 2, (ch + 2) % 3);
    }

    const int g = lane >> 2, t = lane & 3;
    if (mode) {
        // fp32 epilogue
#pragma unroll
        for (int mf = 0; mf < 2; mf++) {
            int row = bm + wm * 32 + mf * 16 + g;
#pragma unroll
            for (int nf = 0; nf < 8; nf++) {
                int col = bn + wn * 64 + nf * 8 + t * 2;
                *(float2*)(Cout + (size_t)row * N + col) =
                    make_float2(acc[mf][nf][0], acc[mf][nf][1]);
                *(float2*)(Cout + (size_t)(row + 8) * N + col) =
                    make_float2(acc[mf][nf][2], acc[mf][nf][3]);
            }
        }
    } else {
        // fp16 epilogue into per-head Q/K/V
        int col0 = bn + wn * 64;
        int mat = col0 >> 10;
        int hh = (col0 & 1023) >> 6;
        __half* BQ = (mat == 0) ? g_q : (mat == 1) ? g_k : g_v;
#pragma unroll
        for (int mf = 0; mf < 2; mf++) {
            int rg = bm + wm * 32 + mf * 16 + g;
            int bb = rg >> 11, l = rg & 2047;
            size_t base = ((size_t)(bb * NHEADS + hh) * SEQ + l) * HDIM;
#pragma unroll
            for (int nf = 0; nf < 8; nf++) {
                int d = nf * 8 + t * 2;
                *(uint32_t*)(BQ + base + d) =
                    pack2h(acc[mf][nf][0], acc[mf][nf][1]);
                *(uint32_t*)(BQ + base + 8 * HDIM + d) =
                    pack2h(acc[mf][nf][2], acc[mf][nf][3]);
            }
        }
    }
}

// ---------------------------------------------------------------------------
// Flash attention, single fp16 products. R5 skeleton: 3-stage KV ring,
// one barrier per tile, exp2 softmax. CTA 256 thr, 128 q rows, KV tile 64.
// smem: 3 x 16KB KV stages (K 8KB | V 8KB) + Q 16KB at 48KB = 64KB total.
// ---------------------------------------------------------------------------
#define AT_SMEM 65536
#define NIT (SEQ / 64)

__global__ __launch_bounds__(256, 2)
void attn_tc()
{
    extern __shared__ char smem[];
    const uint32_t sb = smem_u32(smem);
    const int tid = threadIdx.x, lane = tid & 31, wid = tid >> 5;
    const int b = blockIdx.z, h = blockIdx.y, q0 = blockIdx.x * 128;
    const size_t bh = (size_t)(b * NHEADS + h) * SEQ;

    // ---- stage Q (128x64 fp16 = 16 KB) ----
    const uint32_t QB = sb + 3 * 16384;
    {
        const __half* src = g_q + (bh + q0) * HDIM;
#pragma unroll
        for (int i = 0; i < 4; i++) {
            int idx = i * 256 + tid;          // 0..1023
            int row = idx >> 3, c16 = idx & 7;
            uint32_t sw = QB + row * 128 + ((c16 ^ (row & 7)) << 4);
            CPA16(sw, src + (size_t)row * HDIM + c16 * 8);
        }
        CP_COMMIT();
        asm volatile("cp.async.wait_group 0;" ::: "memory");
    }
    __syncthreads();

    uint32_t qf[4][4];
    {
        int r = wid * 16 + (lane & 15);
        int cl = lane >> 4;
#pragma unroll
        for (int kk = 0; kk < 4; kk++)
            ldsm4(qf[kk], QB + r * 128 + (((kk * 2 + cl) ^ (r & 7)) << 4));
    }

    auto load_kv = [&](int it, int s) {
        const size_t rb = bh + (size_t)it * 64;
        uint32_t dst = sb + s * 16384;
#pragma unroll
        for (int i = 0; i < 2; i++) {
            int idx = i * 256 + tid;          // 0..511
            int row = idx >> 3, c16 = idx & 7;
            uint32_t sw = dst + row * 128 + ((c16 ^ (row & 7)) << 4);
            CPA16(sw, g_k + (rb + row) * HDIM + c16 * 8);
            CPA16(sw + 8192, g_v + (rb + row) * HDIM + c16 * 8);
        }
        CP_COMMIT();
    };

    load_kv(0, 0);
    load_kv(1, 1);

    float o[8][4];
#pragma unroll
    for (int i = 0; i < 8; i++)
#pragma unroll
        for (int j = 0; j < 4; j++) o[i][j] = 0.f;
    float m0 = -1e30f, m1 = -1e30f, l0s = 0.f, l1s = 0.f;

    const int brow0 = ((lane >> 4) & 1) * 8 + (lane & 7);
    const int bc = (lane >> 3) & 1;
    const int vlc = lane >> 4;

    for (int it = 0; it < NIT; it++) {
        const int s = it % 3;
        if (it + 1 < NIT) { asm volatile("cp.async.wait_group 1;" ::: "memory"); }
        else              { asm volatile("cp.async.wait_group 0;" ::: "memory"); }
        __syncthreads();
        if (it + 2 < NIT) load_kv(it + 2, (it + 2) % 3);

        const uint32_t KB = sb + s * 16384;
        const uint32_t VB = KB + 8192;

        // ---- S = Q K^T ----
        float sx[8][4];
#pragma unroll
        for (int i = 0; i < 8; i++)
#pragma unroll
            for (int j = 0; j < 4; j++) sx[i][j] = 0.f;
#pragma unroll
        for (int kk = 0; kk < 4; kk++) {
#pragma unroll
            for (int bp = 0; bp < 4; bp++) {
                uint32_t kfrag[4];
                int r = brow0 + bp * 16;
                int c = kk * 2 + bc;
                ldsm4(kfrag, KB + r * 128 + ((c ^ (r & 7)) << 4));
                mma_f16(sx[2 * bp],     qf[kk], kfrag);
                mma_f16(sx[2 * bp + 1], qf[kk], kfrag + 2);
            }
        }

        // ---- online softmax (exp2 domain) ----
        float rmax0 = -1e30f, rmax1 = -1e30f;
#pragma unroll
        for (int nf = 0; nf < 8; nf++) {
            sx[nf][0] *= QSCALE; sx[nf][1] *= QSCALE;
            sx[nf][2] *= QSCALE; sx[nf][3] *= QSCALE;
            rmax0 = fmaxf(rmax0, fmaxf(sx[nf][0], sx[nf][1]));
            rmax1 = fmaxf(rmax1, fmaxf(sx[nf][2], sx[nf][3]));
        }
        rmax0 = fmaxf(rmax0, __shfl_xor_sync(0xffffffffu, rmax0, 1));
        rmax0 = fmaxf(rmax0, __shfl_xor_sync(0xffffffffu, rmax0, 2));
        rmax1 = fmaxf(rmax1, __shfl_xor_sync(0xffffffffu, rmax1, 1));
        rmax1 = fmaxf(rmax1, __shfl_xor_sync(0xffffffffu, rmax1, 2));
        float mn0 = fmaxf(m0, rmax0), mn1 = fmaxf(m1, rmax1);
        float corr0 = ex2(m0 - mn0), corr1 = ex2(m1 - mn1);
        float sum0 = 0.f, sum1 = 0.f;
#pragma unroll
        for (int nf = 0; nf < 8; nf++) {
            sx[nf][0] = ex2(sx[nf][0] - mn0);
            sx[nf][1] = ex2(sx[nf][1] - mn0);
            sx[nf][2] = ex2(sx[nf][2] - mn1);
            sx[nf][3] = ex2(sx[nf][3] - mn1);
            sum0 += sx[nf][0] + sx[nf][1];
            sum1 += sx[nf][2] + sx[nf][3];
        }
        sum0 += __shfl_xor_sync(0xffffffffu, sum0, 1);
        sum0 += __shfl_xor_sync(0xffffffffu, sum0, 2);
        sum1 += __shfl_xor_sync(0xffffffffu, sum1, 1);
        sum1 += __shfl_xor_sync(0xffffffffu, sum1, 2);
        l0s = l0s * corr0 + sum0;
        l1s = l1s * corr1 + sum1;
        m0 = mn0; m1 = mn1;
#pragma unroll
        for (int nf = 0; nf < 8; nf++) {
            o[nf][0] *= corr0; o[nf][1] *= corr0;
            o[nf][2] *= corr1; o[nf][3] *= corr1;
        }

        // ---- O += P V ----
#pragma unroll
        for (int kk = 0; kk < 4; kk++) {
            uint32_t pf[4];
            pf[0] = pack2h(sx[2 * kk][0], sx[2 * kk][1]);
            pf[1] = pack2h(sx[2 * kk][2], sx[2 * kk][3]);
            pf[2] = pack2h(sx[2 * kk + 1][0], sx[2 * kk + 1][1]);
            pf[3] = pack2h(sx[2 * kk + 1][2], sx[2 * kk + 1][3]);
#pragma unroll
            for (int hp = 0; hp < 4; hp++) {
                uint32_t vf[4];
                int r = kk * 16 + ((lane >> 3) & 1) * 8 + (lane & 7);
                int c = hp * 2 + vlc;
                ldsm4t(vf, VB + r * 128 + ((c ^ (r & 7)) << 4));
                mma_f16(o[2 * hp],     pf, vf);
                mma_f16(o[2 * hp + 1], pf, vf + 2);
            }
        }
    }

    // ---- epilogue: packed [hi | lo] fp16 proj operand ----
    const int g = lane >> 2, t = lane & 3;
    float inv0 = 1.f / l0s, inv1 = 1.f / l1s;
    size_t arow0 = (size_t)b * SEQ + q0 + wid * 16 + g;
#pragma unroll
    for (int nf = 0; nf < 8; nf++) {
        int col = h * 64 + nf * 8 + t * 2;
        {
            float x0 = o[nf][0] * inv0, x1 = o[nf][1] * inv0;
            uint32_t hv = pack2h(x0, x1);
            __half* p = g_aop + arow0 * KP + col;
            *(uint32_t*)(p) = hv;
            *(uint32_t*)(p + DIM) = packresid_h(hv, x0, x1);
        }
        {
            float x0 = o[nf][2] * inv1, x1 = o[nf][3] * inv1;
            uint32_t hv = pack2h(x0, x1);
            __half* p = g_aop + (arow0 + 8) * KP + col;
            *(uint32_t*)(p) = hv;
            *(uint32_t*)(p + DIM) = packresid_h(hv, x0, x1);
        }
    }
}

// ---------------------------------------------------------------------------
// Launch
// ---------------------------------------------------------------------------
extern "C" void kernel_launch(void* const* d_in, const int* in_sizes, int n_in,
                              void* d_out, int out_size)
{
    const float* x      = (const float*)d_in[0];
    const float* w_qkv  = (const float*)d_in[1];
    const float* w_proj = (const float*)d_in[2];
    float* out = (float*)d_out;
    (void)in_sizes; (void)n_in; (void)out_size;

    cudaFuncSetAttribute(gemm_f16k, cudaFuncAttributeMaxDynamicSharedMemorySize, GSMEM);
    cudaFuncSetAttribute(attn_tc, cudaFuncAttributeMaxDynamicSharedMemorySize, AT_SMEM);

    split_x<<<MROWS, 256>>>(x);
    split_w<<<3 * DIM, 256>>>(w_qkv, 0);
    split_w<<<DIM, 256>>>(w_proj, 1);

    // QKV projection (fp16 2-product) + fused fp16 epilogue
    gemm_f16k<<<dim3(3 * DIM / 128, MROWS / 128), 256, GSMEM>>>(0, nullptr, 3 * DIM);

    // attention (single fp16 products), writes packed proj operand
    attn_tc<<<dim3(SEQ / 128, NHEADS, BATCH), 256, AT_SMEM>>>();

    // output projection
    gemm_f16k<<<dim3(DIM / 128, MROWS / 128), 256, GSMEM>>>(1, out, DIM);
}

// round 10
// speedup vs baseline: 2.6319x; 1.4314x over previous
#include <cuda_runtime.h>
#include <cuda_fp16.h>
#include <cstdint>

#define BATCH 2
#define SEQ 2048
#define DIM 1024
#define NHEADS 16
#define HDIM 64
#define QSCALE 0.1803368801111204f   // (1/8) * log2(e)
#define MROWS 4096

// ---------------------------------------------------------------------------
// Scratch (device globals: allocation-free)
// ---------------------------------------------------------------------------
__device__ __align__(16) __half g_xh [(size_t)MROWS * DIM];     // x fp16
__device__ __align__(16) __half g_wqh[(size_t)3 * DIM * DIM];   // w_qkv fp16
__device__ __align__(16) __half g_wph[(size_t)DIM * DIM];       // w_proj fp16
__device__ __align__(16) __half g_aoh[(size_t)MROWS * DIM];     // attn out fp16

// per-head Q/K/V fp16, layout [b][h][l][64]
#define QKV_ELEMS ((size_t)BATCH * NHEADS * SEQ * HDIM)
__device__ __align__(16) __half g_q[QKV_ELEMS];
__device__ __align__(16) __half g_k[QKV_ELEMS];
__device__ __align__(16) __half g_v[QKV_ELEMS];

// ---------------------------------------------------------------------------
// Base-ISA helpers
// ---------------------------------------------------------------------------
__device__ __forceinline__ uint32_t smem_u32(const void* p) {
    uint32_t a;
    asm("{ .reg .u64 t; cvta.to.shared.u64 t, %1; cvt.u32.u64 %0, t; }"
        : "=r"(a) : "l"(p));
    return a;
}
__device__ __forceinline__ void ldsm4(uint32_t* r, uint32_t a) {
    asm volatile("ldmatrix.sync.aligned.m8n8.x4.shared.b16 {%0,%1,%2,%3}, [%4];"
        : "=r"(r[0]), "=r"(r[1]), "=r"(r[2]), "=r"(r[3]) : "r"(a));
}
__device__ __forceinline__ void ldsm4t(uint32_t* r, uint32_t a) {
    asm volatile("ldmatrix.sync.aligned.m8n8.x4.trans.shared.b16 {%0,%1,%2,%3}, [%4];"
        : "=r"(r[0]), "=r"(r[1]), "=r"(r[2]), "=r"(r[3]) : "r"(a));
}
__device__ __forceinline__ void mma_f16(float* c, const uint32_t* a, const uint32_t* b) {
    asm volatile(
        "mma.sync.aligned.m16n8k16.row.col.f32.f16.f16.f32 "
        "{%0,%1,%2,%3}, {%4,%5,%6,%7}, {%8,%9}, {%0,%1,%2,%3};"
        : "+f"(c[0]), "+f"(c[1]), "+f"(c[2]), "+f"(c[3])
        : "r"(a[0]), "r"(a[1]), "r"(a[2]), "r"(a[3]), "r"(b[0]), "r"(b[1]));
}
#define CPA16(d, s) \
    asm volatile("cp.async.cg.shared.global [%0], [%1], 16;" :: "r"(d), "l"(s))
#define CP_COMMIT() asm volatile("cp.async.commit_group;" ::: "memory")

__device__ __forceinline__ float ex2(float x) {
    float r; asm("ex2.approx.f32 %0, %1;" : "=f"(r) : "f"(x)); return r;
}
__device__ __forceinline__ uint32_t pack2h(float x, float y) {
    __half2 t = __floats2half2_rn(x, y);
    return *reinterpret_cast<uint32_t*>(&t);
}

// ---------------------------------------------------------------------------
// Splits: fp32 [rows,1024] -> fp16
// ---------------------------------------------------------------------------
__global__ void split_f16(const float* __restrict__ src, int dst)
{
    __half* out = (dst == 0) ? g_xh : (dst == 1) ? g_wqh : g_wph;
    size_t idx = (size_t)blockIdx.x * 256 + threadIdx.x;
    size_t m = idx >> 8;
    int k = (int)(idx & 255) * 4;
    float4 v = *(const float4*)(src + m * DIM + k);
    *(uint2*)(out + m * DIM + k) = make_uint2(pack2h(v.x, v.y), pack2h(v.z, v.w));
}

// ---------------------------------------------------------------------------
// fp16 HMMA GEMM: C[M,N] = A[M,1024] * B[N,1024]^T, single product.
// 16 chunks of 128 B/row. CTA 128x128, warp 32x64, 3-stage cp.async.
// mode 0: qkv (fp16 Q/K/V epilogue); mode 1: proj (fp32 out).
// ---------------------------------------------------------------------------
#define GST 32768
#define GBOFF 16384
#define GSMEM (3 * GST)
#define NCHT 16

__global__ __launch_bounds__(256, 2)
void gemm_f16(int mode, float* __restrict__ Cout, int N)
{
    const __half* A = mode ? g_aoh : g_xh;
    const __half* B = mode ? g_wph : g_wqh;

    extern __shared__ char sm[];
    const uint32_t sb = smem_u32(sm);
    const int tid = threadIdx.x, lane = tid & 31, wid = tid >> 5;
    const int wm = wid >> 1, wn = wid & 1;
    const int bm = blockIdx.y * 128, bn = blockIdx.x * 128;

    const int ldrow = tid >> 1;
    const int ldc0 = (tid & 1) * 4;

    auto load_stage = [&](int ch, int s) {
        const __half* a = A + (size_t)(bm + ldrow) * DIM + ch * 64;
        const __half* b = B + (size_t)(bn + ldrow) * DIM + ch * 64;
        uint32_t rbase = sb + s * GST + ldrow * 128;
#pragma unroll
        for (int i = 0; i < 4; i++) {
            int c16 = ldc0 + i;
            uint32_t sw = rbase + (uint32_t)((c16 ^ (ldrow & 7)) << 4);
            CPA16(sw, a + c16 * 8);
            CPA16(sw + GBOFF, b + c16 * 8);
        }
        CP_COMMIT();
    };

    load_stage(0, 0);
    load_stage(1, 1);

    float acc[2][8][4];
#pragma unroll
    for (int i = 0; i < 2; i++)
#pragma unroll
        for (int j = 0; j < 8; j++)
#pragma unroll
            for (int q = 0; q < 4; q++) acc[i][j][q] = 0.f;

    const int arow0 = wm * 32 + (lane & 15);
    const int alc = lane >> 4;
    const int brow0 = wn * 64 + ((lane >> 4) & 1) * 8 + (lane & 7);
    const int bc = (lane >> 3) & 1;

    for (int ch = 0; ch < NCHT; ch++) {
        const int s = ch % 3;
        if (ch + 1 < NCHT) { asm volatile("cp.async.wait_group 1;" ::: "memory"); }
        else               { asm volatile("cp.async.wait_group 0;" ::: "memory"); }
        __syncthreads();
        const uint32_t Ab = sb + s * GST;
        const uint32_t Bb = Ab + GBOFF;
#pragma unroll
        for (int kk = 0; kk < 4; kk++) {
            uint32_t a0[4], a1[4];
            {
                int c = kk * 2 + alc;
                int r0 = arow0;
                ldsm4(a0, Ab + r0 * 128 + ((c ^ (r0 & 7)) << 4));
                int r1 = arow0 + 16;
                ldsm4(a1, Ab + r1 * 128 + ((c ^ (r1 & 7)) << 4));
            }
#pragma unroll
            for (int bp = 0; bp < 4; bp++) {
                uint32_t b[4];
                int r = brow0 + bp * 16;
                int c = kk * 2 + bc;
                ldsm4(b, Bb + r * 128 + ((c ^ (r & 7)) << 4));
                mma_f16(acc[0][2 * bp],     a0, b);
                mma_f16(acc[0][2 * bp + 1], a0, b + 2);
                mma_f16(acc[1][2 * bp],     a1, b);
                mma_f16(acc[1][2 * bp + 1], a1, b + 2);
            }
        }
        if (ch + 2 < NCHT) load_stage(ch + 2, (ch + 2) % 3);
    }

    const int g = lane >> 2, t = lane & 3;
    if (mode) {
        // fp32 epilogue
#pragma unroll
        for (int mf = 0; mf < 2; mf++) {
            int row = bm + wm * 32 + mf * 16 + g;
#pragma unroll
            for (int nf = 0; nf < 8; nf++) {
                int col = bn + wn * 64 + nf * 8 + t * 2;
                *(float2*)(Cout + (size_t)row * N + col) =
                    make_float2(acc[mf][nf][0], acc[mf][nf][1]);
                *(float2*)(Cout + (size_t)(row + 8) * N + col) =
                    make_float2(acc[mf][nf][2], acc[mf][nf][3]);
            }
        }
    } else {
        // fp16 epilogue into per-head Q/K/V
        int col0 = bn + wn * 64;
        int mat = col0 >> 10;
        int hh = (col0 & 1023) >> 6;
        __half* BQ = (mat == 0) ? g_q : (mat == 1) ? g_k : g_v;
#pragma unroll
        for (int mf = 0; mf < 2; mf++) {
            int rg = bm + wm * 32 + mf * 16 + g;
            int bb = rg >> 11, l = rg & 2047;
            size_t base = ((size_t)(bb * NHEADS + hh) * SEQ + l) * HDIM;
#pragma unroll
            for (int nf = 0; nf < 8; nf++) {
                int d = nf * 8 + t * 2;
                *(uint32_t*)(BQ + base + d) =
                    pack2h(acc[mf][nf][0], acc[mf][nf][1]);
                *(uint32_t*)(BQ + base + 8 * HDIM + d) =
                    pack2h(acc[mf][nf][2], acc[mf][nf][3]);
            }
        }
    }
}

// ---------------------------------------------------------------------------
// Flash attention, single fp16 products (R9 proven). 3-stage KV ring,
// one barrier per tile, exp2 softmax. CTA 256 thr, 128 q rows, KV tile 64.
// smem: 3 x 16KB KV stages (K 8KB | V 8KB) + Q 16KB at 48KB = 64KB total.
// ---------------------------------------------------------------------------
#define AT_SMEM 65536
#define NIT (SEQ / 64)

__global__ __launch_bounds__(256, 2)
void attn_tc()
{
    extern __shared__ char smem[];
    const uint32_t sb = smem_u32(smem);
    const int tid = threadIdx.x, lane = tid & 31, wid = tid >> 5;
    const int b = blockIdx.z, h = blockIdx.y, q0 = blockIdx.x * 128;
    const size_t bh = (size_t)(b * NHEADS + h) * SEQ;

    // ---- stage Q (128x64 fp16 = 16 KB) ----
    const uint32_t QB = sb + 3 * 16384;
    {
        const __half* src = g_q + (bh + q0) * HDIM;
#pragma unroll
        for (int i = 0; i < 4; i++) {
            int idx = i * 256 + tid;          // 0..1023
            int row = idx >> 3, c16 = idx & 7;
            uint32_t sw = QB + row * 128 + ((c16 ^ (row & 7)) << 4);
            CPA16(sw, src + (size_t)row * HDIM + c16 * 8);
        }
        CP_COMMIT();
        asm volatile("cp.async.wait_group 0;" ::: "memory");
    }
    __syncthreads();

    uint32_t qf[4][4];
    {
        int r = wid * 16 + (lane & 15);
        int cl = lane >> 4;
#pragma unroll
        for (int kk = 0; kk < 4; kk++)
            ldsm4(qf[kk], QB + r * 128 + (((kk * 2 + cl) ^ (r & 7)) << 4));
    }

    auto load_kv = [&](int it, int s) {
        const size_t rb = bh + (size_t)it * 64;
        uint32_t dst = sb + s * 16384;
#pragma unroll
        for (int i = 0; i < 2; i++) {
            int idx = i * 256 + tid;          // 0..511
            int row = idx >> 3, c16 = idx & 7;
            uint32_t sw = dst + row * 128 + ((c16 ^ (row & 7)) << 4);
            CPA16(sw, g_k + (rb + row) * HDIM + c16 * 8);
            CPA16(sw + 8192, g_v + (rb + row) * HDIM + c16 * 8);
        }
        CP_COMMIT();
    };

    load_kv(0, 0);
    load_kv(1, 1);

    float o[8][4];
#pragma unroll
    for (int i = 0; i < 8; i++)
#pragma unroll
        for (int j = 0; j < 4; j++) o[i][j] = 0.f;
    float m0 = -1e30f, m1 = -1e30f, l0s = 0.f, l1s = 0.f;

    const int brow0 = ((lane >> 4) & 1) * 8 + (lane & 7);
    const int bc = (lane >> 3) & 1;
    const int vlc = lane >> 4;

    for (int it = 0; it < NIT; it++) {
        const int s = it % 3;
        if (it + 1 < NIT) { asm volatile("cp.async.wait_group 1;" ::: "memory"); }
        else              { asm volatile("cp.async.wait_group 0;" ::: "memory"); }
        __syncthreads();
        if (it + 2 < NIT) load_kv(it + 2, (it + 2) % 3);

        const uint32_t KB = sb + s * 16384;
        const uint32_t VB = KB + 8192;

        // ---- S = Q K^T ----
        float sx[8][4];
#pragma unroll
        for (int i = 0; i < 8; i++)
#pragma unroll
            for (int j = 0; j < 4; j++) sx[i][j] = 0.f;
#pragma unroll
        for (int kk = 0; kk < 4; kk++) {
#pragma unroll
            for (int bp = 0; bp < 4; bp++) {
                uint32_t kfrag[4];
                int r = brow0 + bp * 16;
                int c = kk * 2 + bc;
                ldsm4(kfrag, KB + r * 128 + ((c ^ (r & 7)) << 4));
                mma_f16(sx[2 * bp],     qf[kk], kfrag);
                mma_f16(sx[2 * bp + 1], qf[kk], kfrag + 2);
            }
        }

        // ---- online softmax (exp2 domain) ----
        float rmax0 = -1e30f, rmax1 = -1e30f;
#pragma unroll
        for (int nf = 0; nf < 8; nf++) {
            sx[nf][0] *= QSCALE; sx[nf][1] *= QSCALE;
            sx[nf][2] *= QSCALE; sx[nf][3] *= QSCALE;
            rmax0 = fmaxf(rmax0, fmaxf(sx[nf][0], sx[nf][1]));
            rmax1 = fmaxf(rmax1, fmaxf(sx[nf][2], sx[nf][3]));
        }
        rmax0 = fmaxf(rmax0, __shfl_xor_sync(0xffffffffu, rmax0, 1));
        rmax0 = fmaxf(rmax0, __shfl_xor_sync(0xffffffffu, rmax0, 2));
        rmax1 = fmaxf(rmax1, __shfl_xor_sync(0xffffffffu, rmax1, 1));
        rmax1 = fmaxf(rmax1, __shfl_xor_sync(0xffffffffu, rmax1, 2));
        float mn0 = fmaxf(m0, rmax0), mn1 = fmaxf(m1, rmax1);
        float corr0 = ex2(m0 - mn0), corr1 = ex2(m1 - mn1);
        float sum0 = 0.f, sum1 = 0.f;
#pragma unroll
        for (int nf = 0; nf < 8; nf++) {
            sx[nf][0] = ex2(sx[nf][0] - mn0);
            sx[nf][1] = ex2(sx[nf][1] - mn0);
            sx[nf][2] = ex2(sx[nf][2] - mn1);
            sx[nf][3] = ex2(sx[nf][3] - mn1);
            sum0 += sx[nf][0] + sx[nf][1];
            sum1 += sx[nf][2] + sx[nf][3];
        }
        sum0 += __shfl_xor_sync(0xffffffffu, sum0, 1);
        sum0 += __shfl_xor_sync(0xffffffffu, sum0, 2);
        sum1 += __shfl_xor_sync(0xffffffffu, sum1, 1);
        sum1 += __shfl_xor_sync(0xffffffffu, sum1, 2);
        l0s = l0s * corr0 + sum0;
        l1s = l1s * corr1 + sum1;
        m0 = mn0; m1 = mn1;
#pragma unroll
        for (int nf = 0; nf < 8; nf++) {
            o[nf][0] *= corr0; o[nf][1] *= corr0;
            o[nf][2] *= corr1; o[nf][3] *= corr1;
        }

        // ---- O += P V ----
#pragma unroll
        for (int kk = 0; kk < 4; kk++) {
            uint32_t pf[4];
            pf[0] = pack2h(sx[2 * kk][0], sx[2 * kk][1]);
            pf[1] = pack2h(sx[2 * kk][2], sx[2 * kk][3]);
            pf[2] = pack2h(sx[2 * kk + 1][0], sx[2 * kk + 1][1]);
            pf[3] = pack2h(sx[2 * kk + 1][2], sx[2 * kk + 1][3]);
#pragma unroll
            for (int hp = 0; hp < 4; hp++) {
                uint32_t vf[4];
                int r = kk * 16 + ((lane >> 3) & 1) * 8 + (lane & 7);
                int c = hp * 2 + vlc;
                ldsm4t(vf, VB + r * 128 + ((c ^ (r & 7)) << 4));
                mma_f16(o[2 * hp],     pf, vf);
                mma_f16(o[2 * hp + 1], pf, vf + 2);
            }
        }
    }

    // ---- epilogue: fp16 proj operand ----
    const int g = lane >> 2, t = lane & 3;
    float inv0 = 1.f / l0s, inv1 = 1.f / l1s;
    size_t arow0 = (size_t)b * SEQ + q0 + wid * 16 + g;
#pragma unroll
    for (int nf = 0; nf < 8; nf++) {
        int col = h * 64 + nf * 8 + t * 2;
        *(uint32_t*)(g_aoh + arow0 * DIM + col) =
            pack2h(o[nf][0] * inv0, o[nf][1] * inv0);
        *(uint32_t*)(g_aoh + (arow0 + 8) * DIM + col) =
            pack2h(o[nf][2] * inv1, o[nf][3] * inv1);
    }
}

// ---------------------------------------------------------------------------
// Launch
// ---------------------------------------------------------------------------
extern "C" void kernel_launch(void* const* d_in, const int* in_sizes, int n_in,
                              void* d_out, int out_size)
{
    const float* x      = (const float*)d_in[0];
    const float* w_qkv  = (const float*)d_in[1];
    const float* w_proj = (const float*)d_in[2];
    float* out = (float*)d_out;
    (void)in_sizes; (void)n_in; (void)out_size;

    cudaFuncSetAttribute(gemm_f16, cudaFuncAttributeMaxDynamicSharedMemorySize, GSMEM);
    cudaFuncSetAttribute(attn_tc, cudaFuncAttributeMaxDynamicSharedMemorySize, AT_SMEM);

    split_f16<<<MROWS, 256>>>(x, 0);
    split_f16<<<3 * DIM, 256>>>(w_qkv, 1);
    split_f16<<<DIM, 256>>>(w_proj, 2);

    // QKV projection (single fp16 product) + fused fp16 epilogue
    gemm_f16<<<dim3(3 * DIM / 128, MROWS / 128), 256, GSMEM>>>(0, nullptr, 3 * DIM);

    // attention (single fp16 products)
    attn_tc<<<dim3(SEQ / 128, NHEADS, BATCH), 256, AT_SMEM>>>();

    // output projection
    gemm_f16<<<dim3(DIM / 128, MROWS / 128), 256, GSMEM>>>(1, out, DIM);
}

// round 11
// speedup vs baseline: 2.6724x; 1.0154x over previous
#include <cuda_runtime.h>
#include <cuda_fp16.h>
#include <cstdint>

#define BATCH 2
#define SEQ 2048
#define DIM 1024
#define NHEADS 16
#define HDIM 64
#define QSCALE 0.1803368801111204f   // (1/8) * log2(e)
#define MROWS 4096

// ---------------------------------------------------------------------------
// Scratch (device globals: allocation-free)
// ---------------------------------------------------------------------------
__device__ __align__(16) __half g_xh [(size_t)MROWS * DIM];     // x fp16
__device__ __align__(16) __half g_wqh[(size_t)3 * DIM * DIM];   // w_qkv fp16
__device__ __align__(16) __half g_wph[(size_t)DIM * DIM];       // w_proj fp16
__device__ __align__(16) __half g_aoh[(size_t)MROWS * DIM];     // attn out fp16

// per-head Q/K/V fp16, layout [b][h][l][64]
#define QKV_ELEMS ((size_t)BATCH * NHEADS * SEQ * HDIM)
__device__ __align__(16) __half g_q[QKV_ELEMS];
__device__ __align__(16) __half g_k[QKV_ELEMS];
__device__ __align__(16) __half g_v[QKV_ELEMS];

// ---------------------------------------------------------------------------
// Base-ISA helpers
// ---------------------------------------------------------------------------
__device__ __forceinline__ uint32_t smem_u32(const void* p) {
    uint32_t a;
    asm("{ .reg .u64 t; cvta.to.shared.u64 t, %1; cvt.u32.u64 %0, t; }"
        : "=r"(a) : "l"(p));
    return a;
}
__device__ __forceinline__ void ldsm4(uint32_t* r, uint32_t a) {
    asm volatile("ldmatrix.sync.aligned.m8n8.x4.shared.b16 {%0,%1,%2,%3}, [%4];"
        : "=r"(r[0]), "=r"(r[1]), "=r"(r[2]), "=r"(r[3]) : "r"(a));
}
__device__ __forceinline__ void ldsm4t(uint32_t* r, uint32_t a) {
    asm volatile("ldmatrix.sync.aligned.m8n8.x4.trans.shared.b16 {%0,%1,%2,%3}, [%4];"
        : "=r"(r[0]), "=r"(r[1]), "=r"(r[2]), "=r"(r[3]) : "r"(a));
}
__device__ __forceinline__ void mma_f16(float* c, const uint32_t* a, const uint32_t* b) {
    asm volatile(
        "mma.sync.aligned.m16n8k16.row.col.f32.f16.f16.f32 "
        "{%0,%1,%2,%3}, {%4,%5,%6,%7}, {%8,%9}, {%0,%1,%2,%3};"
        : "+f"(c[0]), "+f"(c[1]), "+f"(c[2]), "+f"(c[3])
        : "r"(a[0]), "r"(a[1]), "r"(a[2]), "r"(a[3]), "r"(b[0]), "r"(b[1]));
}
#define CPA16(d, s) \
    asm volatile("cp.async.cg.shared.global [%0], [%1], 16;" :: "r"(d), "l"(s))
#define CP_COMMIT() asm volatile("cp.async.commit_group;" ::: "memory")

__device__ __forceinline__ float ex2(float x) {
    float r; asm("ex2.approx.f32 %0, %1;" : "=f"(r) : "f"(x)); return r;
}
__device__ __forceinline__ uint32_t pack2h(float x, float y) {
    __half2 t = __floats2half2_rn(x, y);
    return *reinterpret_cast<uint32_t*>(&t);
}

// ---------------------------------------------------------------------------
// Merged split: one launch converts x, w_qkv, w_proj to fp16.
// grid = 4096 + 3072 + 1024 = 8192 blocks; one block = one 1024-float row.
// ---------------------------------------------------------------------------
__global__ void split_all(const float* __restrict__ x,
                          const float* __restrict__ wq,
                          const float* __restrict__ wp)
{
    int bid = blockIdx.x;
    const float* src;
    __half* dst;
    if (bid < MROWS)                 { src = x  + (size_t)bid * DIM;           dst = g_xh  + (size_t)bid * DIM; }
    else if (bid < MROWS + 3 * DIM)  { src = wq + (size_t)(bid - MROWS) * DIM; dst = g_wqh + (size_t)(bid - MROWS) * DIM; }
    else                             { src = wp + (size_t)(bid - MROWS - 3 * DIM) * DIM;
                                       dst = g_wph + (size_t)(bid - MROWS - 3 * DIM) * DIM; }
    int k = threadIdx.x * 4;
    float4 v = *(const float4*)(src + k);
    *(uint2*)(dst + k) = make_uint2(pack2h(v.x, v.y), pack2h(v.z, v.w));
}

// ---------------------------------------------------------------------------
// fp16 HMMA GEMM: C[M,N] = A[M,1024] * B[N,1024]^T, single product.
// CTA tile 128x64, 256 thr (8 warps as 4m x 2n), warp tile 32x32.
// 16 chunks of 128 B/row, 3-stage cp.async, 3 CTAs/SM (24 warps/SM).
// mode 0: qkv (fp16 Q/K/V epilogue); mode 1: proj (fp32 out).
// ---------------------------------------------------------------------------
#define GST 24576          // A 16K + B 8K per stage
#define GBOFF 16384
#define GSMEM (3 * GST)    // 72 KB
#define NCHT 16

__global__ __launch_bounds__(256, 3)
void gemm_f16(int mode, float* __restrict__ Cout, int N)
{
    const __half* A = mode ? g_aoh : g_xh;
    const __half* B = mode ? g_wph : g_wqh;

    extern __shared__ char sm[];
    const uint32_t sb = smem_u32(sm);
    const int tid = threadIdx.x, lane = tid & 31, wid = tid >> 5;
    const int wm = wid >> 1, wn = wid & 1;
    const int bm = blockIdx.y * 128, bn = blockIdx.x * 64;

    const int lra = tid >> 1;             // A row 0..127
    const int lca = (tid & 1) * 4;        // A col16 base
    const int lrb = tid >> 2;             // B row 0..63
    const int lcb = (tid & 3) * 2;        // B col16 base

    auto load_stage = [&](int ch, int s) {
        const int co = ch * 64;
        uint32_t abase = sb + s * GST + lra * 128;
        const __half* a = A + (size_t)(bm + lra) * DIM + co;
#pragma unroll
        for (int i = 0; i < 4; i++) {
            int c16 = lca + i;
            CPA16(abase + (uint32_t)((c16 ^ (lra & 7)) << 4), a + c16 * 8);
        }
        uint32_t bbase = sb + s * GST + GBOFF + lrb * 128;
        const __half* b = B + (size_t)(bn + lrb) * DIM + co;
#pragma unroll
        for (int i = 0; i < 2; i++) {
            int c16 = lcb + i;
            CPA16(bbase + (uint32_t)((c16 ^ (lrb & 7)) << 4), b + c16 * 8);
        }
        CP_COMMIT();
    };

    load_stage(0, 0);
    load_stage(1, 1);

    float acc[2][4][4];
#pragma unroll
    for (int i = 0; i < 2; i++)
#pragma unroll
        for (int j = 0; j < 4; j++)
#pragma unroll
            for (int q = 0; q < 4; q++) acc[i][j][q] = 0.f;

    const int arow0 = wm * 32 + (lane & 15);
    const int alc = lane >> 4;
    const int brow0 = wn * 32 + ((lane >> 4) & 1) * 8 + (lane & 7);
    const int bc = (lane >> 3) & 1;

    for (int ch = 0; ch < NCHT; ch++) {
        const int s = ch % 3;
        if (ch + 1 < NCHT) { asm volatile("cp.async.wait_group 1;" ::: "memory"); }
        else               { asm volatile("cp.async.wait_group 0;" ::: "memory"); }
        __syncthreads();
        const uint32_t Ab = sb + s * GST;
        const uint32_t Bb = Ab + GBOFF;
#pragma unroll
        for (int kk = 0; kk < 4; kk++) {
            uint32_t a0[4], a1[4];
            {
                int c = kk * 2 + alc;
                int r0 = arow0;
                ldsm4(a0, Ab + r0 * 128 + ((c ^ (r0 & 7)) << 4));
                int r1 = arow0 + 16;
                ldsm4(a1, Ab + r1 * 128 + ((c ^ (r1 & 7)) << 4));
            }
#pragma unroll
            for (int bp = 0; bp < 2; bp++) {
                uint32_t b[4];
                int r = brow0 + bp * 16;
                int c = kk * 2 + bc;
                ldsm4(b, Bb + r * 128 + ((c ^ (r & 7)) << 4));
                mma_f16(acc[0][2 * bp],     a0, b);
                mma_f16(acc[0][2 * bp + 1], a0, b + 2);
                mma_f16(acc[1][2 * bp],     a1, b);
                mma_f16(acc[1][2 * bp + 1], a1, b + 2);
            }
        }
        if (ch + 2 < NCHT) load_stage(ch + 2, (ch + 2) % 3);
    }

    const int g = lane >> 2, t = lane & 3;
    if (mode) {
        // fp32 epilogue
#pragma unroll
        for (int mf = 0; mf < 2; mf++) {
            int row = bm + wm * 32 + mf * 16 + g;
#pragma unroll
            for (int nf = 0; nf < 4; nf++) {
                int col = bn + wn * 32 + nf * 8 + t * 2;
                *(float2*)(Cout + (size_t)row * N + col) =
                    make_float2(acc[mf][nf][0], acc[mf][nf][1]);
                *(float2*)(Cout + (size_t)(row + 8) * N + col) =
                    make_float2(acc[mf][nf][2], acc[mf][nf][3]);
            }
        }
    } else {
        // fp16 epilogue into per-head Q/K/V
        int col0 = bn + wn * 32;
        int mat = col0 >> 10;
        int cm = col0 & 1023;
        int hh = cm >> 6;
        int d0 = cm & 63;                 // 0 or 32
        __half* BQ = (mat == 0) ? g_q : (mat == 1) ? g_k : g_v;
#pragma unroll
        for (int mf = 0; mf < 2; mf++) {
            int rg = bm + wm * 32 + mf * 16 + g;
            int bb = rg >> 11, l = rg & 2047;
            size_t base = ((size_t)(bb * NHEADS + hh) * SEQ + l) * HDIM;
#pragma unroll
            for (int nf = 0; nf < 4; nf++) {
                int d = d0 + nf * 8 + t * 2;
                *(uint32_t*)(BQ + base + d) =
                    pack2h(acc[mf][nf][0], acc[mf][nf][1]);
                *(uint32_t*)(BQ + base + 8 * HDIM + d) =
                    pack2h(acc[mf][nf][2], acc[mf][nf][3]);
            }
        }
    }
}

// ---------------------------------------------------------------------------
// Flash attention, single fp16 products (R10 proven, unchanged).
// ---------------------------------------------------------------------------
#define AT_SMEM 65536
#define NIT (SEQ / 64)

__global__ __launch_bounds__(256, 2)
void attn_tc()
{
    extern __shared__ char smem[];
    const uint32_t sb = smem_u32(smem);
    const int tid = threadIdx.x, lane = tid & 31, wid = tid >> 5;
    const int b = blockIdx.z, h = blockIdx.y, q0 = blockIdx.x * 128;
    const size_t bh = (size_t)(b * NHEADS + h) * SEQ;

    // ---- stage Q (128x64 fp16 = 16 KB) ----
    const uint32_t QB = sb + 3 * 16384;
    {
        const __half* src = g_q + (bh + q0) * HDIM;
#pragma unroll
        for (int i = 0; i < 4; i++) {
            int idx = i * 256 + tid;
            int row = idx >> 3, c16 = idx & 7;
            uint32_t sw = QB + row * 128 + ((c16 ^ (row & 7)) << 4);
            CPA16(sw, src + (size_t)row * HDIM + c16 * 8);
        }
        CP_COMMIT();
        asm volatile("cp.async.wait_group 0;" ::: "memory");
    }
    __syncthreads();

    uint32_t qf[4][4];
    {
        int r = wid * 16 + (lane & 15);
        int cl = lane >> 4;
#pragma unroll
        for (int kk = 0; kk < 4; kk++)
            ldsm4(qf[kk], QB + r * 128 + (((kk * 2 + cl) ^ (r & 7)) << 4));
    }

    auto load_kv = [&](int it, int s) {
        const size_t rb = bh + (size_t)it * 64;
        uint32_t dst = sb + s * 16384;
#pragma unroll
        for (int i = 0; i < 2; i++) {
            int idx = i * 256 + tid;
            int row = idx >> 3, c16 = idx & 7;
            uint32_t sw = dst + row * 128 + ((c16 ^ (row & 7)) << 4);
            CPA16(sw, g_k + (rb + row) * HDIM + c16 * 8);
            CPA16(sw + 8192, g_v + (rb + row) * HDIM + c16 * 8);
        }
        CP_COMMIT();
    };

    load_kv(0, 0);
    load_kv(1, 1);

    float o[8][4];
#pragma unroll
    for (int i = 0; i < 8; i++)
#pragma unroll
        for (int j = 0; j < 4; j++) o[i][j] = 0.f;
    float m0 = -1e30f, m1 = -1e30f, l0s = 0.f, l1s = 0.f;

    const int brow0 = ((lane >> 4) & 1) * 8 + (lane & 7);
    const int bc = (lane >> 3) & 1;
    const int vlc = lane >> 4;

    for (int it = 0; it < NIT; it++) {
        const int s = it % 3;
        if (it + 1 < NIT) { asm volatile("cp.async.wait_group 1;" ::: "memory"); }
        else              { asm volatile("cp.async.wait_group 0;" ::: "memory"); }
        __syncthreads();
        if (it + 2 < NIT) load_kv(it + 2, (it + 2) % 3);

        const uint32_t KB = sb + s * 16384;
        const uint32_t VB = KB + 8192;

        // ---- S = Q K^T ----
        float sx[8][4];
#pragma unroll
        for (int i = 0; i < 8; i++)
#pragma unroll
            for (int j = 0; j < 4; j++) sx[i][j] = 0.f;
#pragma unroll
        for (int kk = 0; kk < 4; kk++) {
#pragma unroll
            for (int bp = 0; bp < 4; bp++) {
                uint32_t kfrag[4];
                int r = brow0 + bp * 16;
                int c = kk * 2 + bc;
                ldsm4(kfrag, KB + r * 128 + ((c ^ (r & 7)) << 4));
                mma_f16(sx[2 * bp],     qf[kk], kfrag);
                mma_f16(sx[2 * bp + 1], qf[kk], kfrag + 2);
            }
        }

        // ---- online softmax (exp2 domain) ----
        float rmax0 = -1e30f, rmax1 = -1e30f;
#pragma unroll
        for (int nf = 0; nf < 8; nf++) {
            sx[nf][0] *= QSCALE; sx[nf][1] *= QSCALE;
            sx[nf][2] *= QSCALE; sx[nf][3] *= QSCALE;
            rmax0 = fmaxf(rmax0, fmaxf(sx[nf][0], sx[nf][1]));
            rmax1 = fmaxf(rmax1, fmaxf(sx[nf][2], sx[nf][3]));
        }
        rmax0 = fmaxf(rmax0, __shfl_xor_sync(0xffffffffu, rmax0, 1));
        rmax0 = fmaxf(rmax0, __shfl_xor_sync(0xffffffffu, rmax0, 2));
        rmax1 = fmaxf(rmax1, __shfl_xor_sync(0xffffffffu, rmax1, 1));
        rmax1 = fmaxf(rmax1, __shfl_xor_sync(0xffffffffu, rmax1, 2));
        float mn0 = fmaxf(m0, rmax0), mn1 = fmaxf(m1, rmax1);
        float corr0 = ex2(m0 - mn0), corr1 = ex2(m1 - mn1);
        float sum0 = 0.f, sum1 = 0.f;
#pragma unroll
        for (int nf = 0; nf < 8; nf++) {
            sx[nf][0] = ex2(sx[nf][0] - mn0);
            sx[nf][1] = ex2(sx[nf][1] - mn0);
            sx[nf][2] = ex2(sx[nf][2] - mn1);
            sx[nf][3] = ex2(sx[nf][3] - mn1);
            sum0 += sx[nf][0] + sx[nf][1];
            sum1 += sx[nf][2] + sx[nf][3];
        }
        sum0 += __shfl_xor_sync(0xffffffffu, sum0, 1);
        sum0 += __shfl_xor_sync(0xffffffffu, sum0, 2);
        sum1 += __shfl_xor_sync(0xffffffffu, sum1, 1);
        sum1 += __shfl_xor_sync(0xffffffffu, sum1, 2);
        l0s = l0s * corr0 + sum0;
        l1s = l1s * corr1 + sum1;
        m0 = mn0; m1 = mn1;
#pragma unroll
        for (int nf = 0; nf < 8; nf++) {
            o[nf][0] *= corr0; o[nf][1] *= corr0;
            o[nf][2] *= corr1; o[nf][3] *= corr1;
        }

        // ---- O += P V ----
#pragma unroll
        for (int kk = 0; kk < 4; kk++) {
            uint32_t pf[4];
            pf[0] = pack2h(sx[2 * kk][0], sx[2 * kk][1]);
            pf[1] = pack2h(sx[2 * kk][2], sx[2 * kk][3]);
            pf[2] = pack2h(sx[2 * kk + 1][0], sx[2 * kk + 1][1]);
            pf[3] = pack2h(sx[2 * kk + 1][2], sx[2 * kk + 1][3]);
#pragma unroll
            for (int hp = 0; hp < 4; hp++) {
                uint32_t vf[4];
                int r = kk * 16 + ((lane >> 3) & 1) * 8 + (lane & 7);
                int c = hp * 2 + vlc;
                ldsm4t(vf, VB + r * 128 + ((c ^ (r & 7)) << 4));
                mma_f16(o[2 * hp],     pf, vf);
                mma_f16(o[2 * hp + 1], pf, vf + 2);
            }
        }
    }

    // ---- epilogue: fp16 proj operand ----
    const int g = lane >> 2, t = lane & 3;
    float inv0 = 1.f / l0s, inv1 = 1.f / l1s;
    size_t arow0 = (size_t)b * SEQ + q0 + wid * 16 + g;
#pragma unroll
    for (int nf = 0; nf < 8; nf++) {
        int col = h * 64 + nf * 8 + t * 2;
        *(uint32_t*)(g_aoh + arow0 * DIM + col) =
            pack2h(o[nf][0] * inv0, o[nf][1] * inv0);
        *(uint32_t*)(g_aoh + (arow0 + 8) * DIM + col) =
            pack2h(o[nf][2] * inv1, o[nf][3] * inv1);
    }
}

// ---------------------------------------------------------------------------
// Launch
// ---------------------------------------------------------------------------
extern "C" void kernel_launch(void* const* d_in, const int* in_sizes, int n_in,
                              void* d_out, int out_size)
{
    const float* x      = (const float*)d_in[0];
    const float* w_qkv  = (const float*)d_in[1];
    const float* w_proj = (const float*)d_in[2];
    float* out = (float*)d_out;
    (void)in_sizes; (void)n_in; (void)out_size;

    cudaFuncSetAttribute(gemm_f16, cudaFuncAttributeMaxDynamicSharedMemorySize, GSMEM);
    cudaFuncSetAttribute(attn_tc, cudaFuncAttributeMaxDynamicSharedMemorySize, AT_SMEM);

    // merged fp32 -> fp16 conversion (one launch)
    split_all<<<MROWS + 3 * DIM + DIM, 256>>>(x, w_qkv, w_proj);

    // QKV projection (128x64 tiles, 3 CTAs/SM) + fused fp16 epilogue
    gemm_f16<<<dim3(3 * DIM / 64, MROWS / 128), 256, GSMEM>>>(0, nullptr, 3 * DIM);

    // attention (single fp16 products)
    attn_tc<<<dim3(SEQ / 128, NHEADS, BATCH), 256, AT_SMEM>>>();

    // output projection
    gemm_f16<<<dim3(DIM / 64, MROWS / 128), 256, GSMEM>>>(1, out, DIM);
}

// round 12
// speedup vs baseline: 2.7575x; 1.0319x over previous
#include <cuda_runtime.h>
#include <cuda_fp16.h>
#include <cstdint>

#define BATCH 2
#define SEQ 2048
#define DIM 1024
#define NHEADS 16
#define HDIM 64
#define QSCALE 0.1803368801111204f   // (1/8) * log2(e)
#define MROWS 4096

// ---------------------------------------------------------------------------
// Scratch (device globals: allocation-free)
// ---------------------------------------------------------------------------
__device__ __align__(16) __half g_xh [(size_t)MROWS * DIM];
__device__ __align__(16) __half g_wqh[(size_t)3 * DIM * DIM];
__device__ __align__(16) __half g_wph[(size_t)DIM * DIM];
__device__ __align__(16) __half g_aoh[(size_t)MROWS * DIM];

#define QKV_ELEMS ((size_t)BATCH * NHEADS * SEQ * HDIM)
__device__ __align__(16) __half g_q[QKV_ELEMS];   // pre-scaled by QSCALE
__device__ __align__(16) __half g_k[QKV_ELEMS];
__device__ __align__(16) __half g_v[QKV_ELEMS];

// ---------------------------------------------------------------------------
// Base-ISA helpers
// ---------------------------------------------------------------------------
__device__ __forceinline__ uint32_t smem_u32(const void* p) {
    uint32_t a;
    asm("{ .reg .u64 t; cvta.to.shared.u64 t, %1; cvt.u32.u64 %0, t; }"
        : "=r"(a) : "l"(p));
    return a;
}
__device__ __forceinline__ void ldsm4(uint32_t* r, uint32_t a) {
    asm volatile("ldmatrix.sync.aligned.m8n8.x4.shared.b16 {%0,%1,%2,%3}, [%4];"
        : "=r"(r[0]), "=r"(r[1]), "=r"(r[2]), "=r"(r[3]) : "r"(a));
}
__device__ __forceinline__ void ldsm4t(uint32_t* r, uint32_t a) {
    asm volatile("ldmatrix.sync.aligned.m8n8.x4.trans.shared.b16 {%0,%1,%2,%3}, [%4];"
        : "=r"(r[0]), "=r"(r[1]), "=r"(r[2]), "=r"(r[3]) : "r"(a));
}
__device__ __forceinline__ void mma_f16(float* c, const uint32_t* a, const uint32_t* b) {
    asm volatile(
        "mma.sync.aligned.m16n8k16.row.col.f32.f16.f16.f32 "
        "{%0,%1,%2,%3}, {%4,%5,%6,%7}, {%8,%9}, {%0,%1,%2,%3};"
        : "+f"(c[0]), "+f"(c[1]), "+f"(c[2]), "+f"(c[3])
        : "r"(a[0]), "r"(a[1]), "r"(a[2]), "r"(a[3]), "r"(b[0]), "r"(b[1]));
}
#define CPA16(d, s) \
    asm volatile("cp.async.cg.shared.global [%0], [%1], 16;" :: "r"(d), "l"(s))
#define CP_COMMIT() asm volatile("cp.async.commit_group;" ::: "memory")

__device__ __forceinline__ float ex2(float x) {
    float r; asm("ex2.approx.f32 %0, %1;" : "=f"(r) : "f"(x)); return r;
}
__device__ __forceinline__ uint32_t pack2h(float x, float y) {
    __half2 t = __floats2half2_rn(x, y);
    return *reinterpret_cast<uint32_t*>(&t);
}

// ---------------------------------------------------------------------------
// Merged split: one launch converts x, w_qkv, w_proj to fp16.
// ---------------------------------------------------------------------------
__global__ void split_all(const float* __restrict__ x,
                          const float* __restrict__ wq,
                          const float* __restrict__ wp)
{
    int bid = blockIdx.x;
    const float* src;
    __half* dst;
    if (bid < MROWS)                 { src = x  + (size_t)bid * DIM;           dst = g_xh  + (size_t)bid * DIM; }
    else if (bid < MROWS + 3 * DIM)  { src = wq + (size_t)(bid - MROWS) * DIM; dst = g_wqh + (size_t)(bid - MROWS) * DIM; }
    else                             { src = wp + (size_t)(bid - MROWS - 3 * DIM) * DIM;
                                       dst = g_wph + (size_t)(bid - MROWS - 3 * DIM) * DIM; }
    int k = threadIdx.x * 4;
    float4 v = *(const float4*)(src + k);
    *(uint2*)(dst + k) = make_uint2(pack2h(v.x, v.y), pack2h(v.z, v.w));
}

// ---------------------------------------------------------------------------
// QKV GEMM (R11 config): CTA 128x64, 3 CTAs/SM, fused fp16 Q/K/V epilogue.
// Q gets pre-multiplied by QSCALE.
// ---------------------------------------------------------------------------
#define GST 24576
#define GBOFF 16384
#define GSMEM (3 * GST)
#define NCHT 16

__global__ __launch_bounds__(256, 3)
void gemm_qkv()
{
    extern __shared__ char sm[];
    const uint32_t sb = smem_u32(sm);
    const int tid = threadIdx.x, lane = tid & 31, wid = tid >> 5;
    const int wm = wid >> 1, wn = wid & 1;
    const int bm = blockIdx.y * 128, bn = blockIdx.x * 64;

    const int lra = tid >> 1;
    const int lca = (tid & 1) * 4;
    const int lrb = tid >> 2;
    const int lcb = (tid & 3) * 2;

    auto load_stage = [&](int ch, int s) {
        const int co = ch * 64;
        uint32_t abase = sb + s * GST + lra * 128;
        const __half* a = g_xh + (size_t)(bm + lra) * DIM + co;
#pragma unroll
        for (int i = 0; i < 4; i++) {
            int c16 = lca + i;
            CPA16(abase + (uint32_t)((c16 ^ (lra & 7)) << 4), a + c16 * 8);
        }
        uint32_t bbase = sb + s * GST + GBOFF + lrb * 128;
        const __half* b = g_wqh + (size_t)(bn + lrb) * DIM + co;
#pragma unroll
        for (int i = 0; i < 2; i++) {
            int c16 = lcb + i;
            CPA16(bbase + (uint32_t)((c16 ^ (lrb & 7)) << 4), b + c16 * 8);
        }
        CP_COMMIT();
    };

    load_stage(0, 0);
    load_stage(1, 1);

    float acc[2][4][4];
#pragma unroll
    for (int i = 0; i < 2; i++)
#pragma unroll
        for (int j = 0; j < 4; j++)
#pragma unroll
            for (int q = 0; q < 4; q++) acc[i][j][q] = 0.f;

    const int arow0 = wm * 32 + (lane & 15);
    const int alc = lane >> 4;
    const int brow0 = wn * 32 + ((lane >> 4) & 1) * 8 + (lane & 7);
    const int bc = (lane >> 3) & 1;

    for (int ch = 0; ch < NCHT; ch++) {
        const int s = ch % 3;
        if (ch + 1 < NCHT) { asm volatile("cp.async.wait_group 1;" ::: "memory"); }
        else               { asm volatile("cp.async.wait_group 0;" ::: "memory"); }
        __syncthreads();
        const uint32_t Ab = sb + s * GST;
        const uint32_t Bb = Ab + GBOFF;
#pragma unroll
        for (int kk = 0; kk < 4; kk++) {
            uint32_t a0[4], a1[4];
            {
                int c = kk * 2 + alc;
                int r0 = arow0;
                ldsm4(a0, Ab + r0 * 128 + ((c ^ (r0 & 7)) << 4));
                int r1 = arow0 + 16;
                ldsm4(a1, Ab + r1 * 128 + ((c ^ (r1 & 7)) << 4));
            }
#pragma unroll
            for (int bp = 0; bp < 2; bp++) {
                uint32_t b[4];
                int r = brow0 + bp * 16;
                int c = kk * 2 + bc;
                ldsm4(b, Bb + r * 128 + ((c ^ (r & 7)) << 4));
                mma_f16(acc[0][2 * bp],     a0, b);
                mma_f16(acc[0][2 * bp + 1], a0, b + 2);
                mma_f16(acc[1][2 * bp],     a1, b);
                mma_f16(acc[1][2 * bp + 1], a1, b + 2);
            }
        }
        if (ch + 2 < NCHT) load_stage(ch + 2, (ch + 2) % 3);
    }

    // fp16 epilogue into per-head Q/K/V (Q pre-scaled by QSCALE)
    const int g = lane >> 2, t = lane & 3;
    int col0 = bn + wn * 32;
    int mat = col0 >> 10;
    int cm = col0 & 1023;
    int hh = cm >> 6;
    int d0 = cm & 63;
    __half* BQ = (mat == 0) ? g_q : (mat == 1) ? g_k : g_v;
    const float qs = (mat == 0) ? QSCALE : 1.0f;
#pragma unroll
    for (int mf = 0; mf < 2; mf++) {
        int rg = bm + wm * 32 + mf * 16 + g;
        int bb = rg >> 11, l = rg & 2047;
        size_t base = ((size_t)(bb * NHEADS + hh) * SEQ + l) * HDIM;
#pragma unroll
        for (int nf = 0; nf < 4; nf++) {
            int d = d0 + nf * 8 + t * 2;
            *(uint32_t*)(BQ + base + d) =
                pack2h(acc[mf][nf][0] * qs, acc[mf][nf][1] * qs);
            *(uint32_t*)(BQ + base + 8 * HDIM + d) =
                pack2h(acc[mf][nf][2] * qs, acc[mf][nf][3] * qs);
        }
    }
}

// ---------------------------------------------------------------------------
// Proj GEMM (R10 config): CTA 128x128, 2 CTAs/SM -> 256 CTAs = single wave.
// ---------------------------------------------------------------------------
#define PST 32768
#define PBOFF 16384
#define PSMEM (3 * PST)

__global__ __launch_bounds__(256, 2)
void gemm_proj(float* __restrict__ Cout)
{
    const int N = DIM;
    extern __shared__ char sm[];
    const uint32_t sb = smem_u32(sm);
    const int tid = threadIdx.x, lane = tid & 31, wid = tid >> 5;
    const int wm = wid >> 1, wn = wid & 1;
    const int bm = blockIdx.y * 128, bn = blockIdx.x * 128;

    const int ldrow = tid >> 1;
    const int ldc0 = (tid & 1) * 4;

    auto load_stage = [&](int ch, int s) {
        const __half* a = g_aoh + (size_t)(bm + ldrow) * DIM + ch * 64;
        const __half* b = g_wph + (size_t)(bn + ldrow) * DIM + ch * 64;
        uint32_t rbase = sb + s * PST + ldrow * 128;
#pragma unroll
        for (int i = 0; i < 4; i++) {
            int c16 = ldc0 + i;
            uint32_t sw = rbase + (uint32_t)((c16 ^ (ldrow & 7)) << 4);
            CPA16(sw, a + c16 * 8);
            CPA16(sw + PBOFF, b + c16 * 8);
        }
        CP_COMMIT();
    };

    load_stage(0, 0);
    load_stage(1, 1);

    float acc[2][8][4];
#pragma unroll
    for (int i = 0; i < 2; i++)
#pragma unroll
        for (int j = 0; j < 8; j++)
#pragma unroll
            for (int q = 0; q < 4; q++) acc[i][j][q] = 0.f;

    const int arow0 = wm * 32 + (lane & 15);
    const int alc = lane >> 4;
    const int brow0 = wn * 64 + ((lane >> 4) & 1) * 8 + (lane & 7);
    const int bc = (lane >> 3) & 1;

    for (int ch = 0; ch < NCHT; ch++) {
        const int s = ch % 3;
        if (ch + 1 < NCHT) { asm volatile("cp.async.wait_group 1;" ::: "memory"); }
        else               { asm volatile("cp.async.wait_group 0;" ::: "memory"); }
        __syncthreads();
        const uint32_t Ab = sb + s * PST;
        const uint32_t Bb = Ab + PBOFF;
#pragma unroll
        for (int kk = 0; kk < 4; kk++) {
            uint32_t a0[4], a1[4];
            {
                int c = kk * 2 + alc;
                int r0 = arow0;
                ldsm4(a0, Ab + r0 * 128 + ((c ^ (r0 & 7)) << 4));
                int r1 = arow0 + 16;
                ldsm4(a1, Ab + r1 * 128 + ((c ^ (r1 & 7)) << 4));
            }
#pragma unroll
            for (int bp = 0; bp < 4; bp++) {
                uint32_t b[4];
                int r = brow0 + bp * 16;
                int c = kk * 2 + bc;
                ldsm4(b, Bb + r * 128 + ((c ^ (r & 7)) << 4));
                mma_f16(acc[0][2 * bp],     a0, b);
                mma_f16(acc[0][2 * bp + 1], a0, b + 2);
                mma_f16(acc[1][2 * bp],     a1, b);
                mma_f16(acc[1][2 * bp + 1], a1, b + 2);
            }
        }
        if (ch + 2 < NCHT) load_stage(ch + 2, (ch + 2) % 3);
    }

    const int g = lane >> 2, t = lane & 3;
#pragma unroll
    for (int mf = 0; mf < 2; mf++) {
        int row = bm + wm * 32 + mf * 16 + g;
#pragma unroll
        for (int nf = 0; nf < 8; nf++) {
            int col = bn + wn * 64 + nf * 8 + t * 2;
            *(float2*)(Cout + (size_t)row * N + col) =
                make_float2(acc[mf][nf][0], acc[mf][nf][1]);
            *(float2*)(Cout + (size_t)(row + 8) * N + col) =
                make_float2(acc[mf][nf][2], acc[mf][nf][3]);
        }
    }
}

// ---------------------------------------------------------------------------
// Flash attention (R10 proven). Q pre-scaled, so no QSCALE multiplies here.
// ---------------------------------------------------------------------------
#define AT_SMEM 65536
#define NIT (SEQ / 64)

__global__ __launch_bounds__(256, 2)
void attn_tc()
{
    extern __shared__ char smem[];
    const uint32_t sb = smem_u32(smem);
    const int tid = threadIdx.x, lane = tid & 31, wid = tid >> 5;
    const int b = blockIdx.z, h = blockIdx.y, q0 = blockIdx.x * 128;
    const size_t bh = (size_t)(b * NHEADS + h) * SEQ;

    // ---- stage Q (128x64 fp16 = 16 KB) ----
    const uint32_t QB = sb + 3 * 16384;
    {
        const __half* src = g_q + (bh + q0) * HDIM;
#pragma unroll
        for (int i = 0; i < 4; i++) {
            int idx = i * 256 + tid;
            int row = idx >> 3, c16 = idx & 7;
            uint32_t sw = QB + row * 128 + ((c16 ^ (row & 7)) << 4);
            CPA16(sw, src + (size_t)row * HDIM + c16 * 8);
        }
        CP_COMMIT();
        asm volatile("cp.async.wait_group 0;" ::: "memory");
    }
    __syncthreads();

    uint32_t qf[4][4];
    {
        int r = wid * 16 + (lane & 15);
        int cl = lane >> 4;
#pragma unroll
        for (int kk = 0; kk < 4; kk++)
            ldsm4(qf[kk], QB + r * 128 + (((kk * 2 + cl) ^ (r & 7)) << 4));
    }

    auto load_kv = [&](int it, int s) {
        const size_t rb = bh + (size_t)it * 64;
        uint32_t dst = sb + s * 16384;
#pragma unroll
        for (int i = 0; i < 2; i++) {
            int idx = i * 256 + tid;
            int row = idx >> 3, c16 = idx & 7;
            uint32_t sw = dst + row * 128 + ((c16 ^ (row & 7)) << 4);
            CPA16(sw, g_k + (rb + row) * HDIM + c16 * 8);
            CPA16(sw + 8192, g_v + (rb + row) * HDIM + c16 * 8);
        }
        CP_COMMIT();
    };

    load_kv(0, 0);
    load_kv(1, 1);

    float o[8][4];
#pragma unroll
    for (int i = 0; i < 8; i++)
#pragma unroll
        for (int j = 0; j < 4; j++) o[i][j] = 0.f;
    float m0 = -1e30f, m1 = -1e30f, l0s = 0.f, l1s = 0.f;

    const int brow0 = ((lane >> 4) & 1) * 8 + (lane & 7);
    const int bc = (lane >> 3) & 1;
    const int vlc = lane >> 4;

    for (int it = 0; it < NIT; it++) {
        const int s = it % 3;
        if (it + 1 < NIT) { asm volatile("cp.async.wait_group 1;" ::: "memory"); }
        else              { asm volatile("cp.async.wait_group 0;" ::: "memory"); }
        __syncthreads();
        if (it + 2 < NIT) load_kv(it + 2, (it + 2) % 3);

        const uint32_t KB = sb + s * 16384;
        const uint32_t VB = KB + 8192;

        // ---- S = Q K^T (already in exp2 domain via pre-scaled Q) ----
        float sx[8][4];
#pragma unroll
        for (int i = 0; i < 8; i++)
#pragma unroll
            for (int j = 0; j < 4; j++) sx[i][j] = 0.f;
#pragma unroll
        for (int kk = 0; kk < 4; kk++) {
#pragma unroll
            for (int bp = 0; bp < 4; bp++) {
                uint32_t kfrag[4];
                int r = brow0 + bp * 16;
                int c = kk * 2 + bc;
                ldsm4(kfrag, KB + r * 128 + ((c ^ (r & 7)) << 4));
                mma_f16(sx[2 * bp],     qf[kk], kfrag);
                mma_f16(sx[2 * bp + 1], qf[kk], kfrag + 2);
            }
        }

        // ---- online softmax (exp2 domain) ----
        float rmax0 = -1e30f, rmax1 = -1e30f;
#pragma unroll
        for (int nf = 0; nf < 8; nf++) {
            rmax0 = fmaxf(rmax0, fmaxf(sx[nf][0], sx[nf][1]));
            rmax1 = fmaxf(rmax1, fmaxf(sx[nf][2], sx[nf][3]));
        }
        rmax0 = fmaxf(rmax0, __shfl_xor_sync(0xffffffffu, rmax0, 1));
        rmax0 = fmaxf(rmax0, __shfl_xor_sync(0xffffffffu, rmax0, 2));
        rmax1 = fmaxf(rmax1, __shfl_xor_sync(0xffffffffu, rmax1, 1));
        rmax1 = fmaxf(rmax1, __shfl_xor_sync(0xffffffffu, rmax1, 2));
        float mn0 = fmaxf(m0, rmax0), mn1 = fmaxf(m1, rmax1);
        float corr0 = ex2(m0 - mn0), corr1 = ex2(m1 - mn1);
        float sum0 = 0.f, sum1 = 0.f;
#pragma unroll
        for (int nf = 0; nf < 8; nf++) {
            sx[nf][0] = ex2(sx[nf][0] - mn0);
            sx[nf][1] = ex2(sx[nf][1] - mn0);
            sx[nf][2] = ex2(sx[nf][2] - mn1);
            sx[nf][3] = ex2(sx[nf][3] - mn1);
            sum0 += sx[nf][0] + sx[nf][1];
            sum1 += sx[nf][2] + sx[nf][3];
        }
        sum0 += __shfl_xor_sync(0xffffffffu, sum0, 1);
        sum0 += __shfl_xor_sync(0xffffffffu, sum0, 2);
        sum1 += __shfl_xor_sync(0xffffffffu, sum1, 1);
        sum1 += __shfl_xor_sync(0xffffffffu, sum1, 2);
        l0s = l0s * corr0 + sum0;
        l1s = l1s * corr1 + sum1;
        m0 = mn0; m1 = mn1;
#pragma unroll
        for (int nf = 0; nf < 8; nf++) {
            o[nf][0] *= corr0; o[nf][1] *= corr0;
            o[nf][2] *= corr1; o[nf][3] *= corr1;
        }

        // ---- O += P V ----
#pragma unroll
        for (int kk = 0; kk < 4; kk++) {
            uint32_t pf[4];
            pf[0] = pack2h(sx[2 * kk][0], sx[2 * kk][1]);
            pf[1] = pack2h(sx[2 * kk][2], sx[2 * kk][3]);
            pf[2] = pack2h(sx[2 * kk + 1][0], sx[2 * kk + 1][1]);
            pf[3] = pack2h(sx[2 * kk + 1][2], sx[2 * kk + 1][3]);
#pragma unroll
            for (int hp = 0; hp < 4; hp++) {
                uint32_t vf[4];
                int r = kk * 16 + ((lane >> 3) & 1) * 8 + (lane & 7);
                int c = hp * 2 + vlc;
                ldsm4t(vf, VB + r * 128 + ((c ^ (r & 7)) << 4));
                mma_f16(o[2 * hp],     pf, vf);
                mma_f16(o[2 * hp + 1], pf, vf + 2);
            }
        }
    }

    // ---- epilogue: fp16 proj operand ----
    const int g = lane >> 2, t = lane & 3;
    float inv0 = 1.f / l0s, inv1 = 1.f / l1s;
    size_t arow0 = (size_t)b * SEQ + q0 + wid * 16 + g;
#pragma unroll
    for (int nf = 0; nf < 8; nf++) {
        int col = h * 64 + nf * 8 + t * 2;
        *(uint32_t*)(g_aoh + arow0 * DIM + col) =
            pack2h(o[nf][0] * inv0, o[nf][1] * inv0);
        *(uint32_t*)(g_aoh + (arow0 + 8) * DIM + col) =
            pack2h(o[nf][2] * inv1, o[nf][3] * inv1);
    }
}

// ---------------------------------------------------------------------------
// Launch
// ---------------------------------------------------------------------------
extern "C" void kernel_launch(void* const* d_in, const int* in_sizes, int n_in,
                              void* d_out, int out_size)
{
    const float* x      = (const float*)d_in[0];
    const float* w_qkv  = (const float*)d_in[1];
    const float* w_proj = (const float*)d_in[2];
    float* out = (float*)d_out;
    (void)in_sizes; (void)n_in; (void)out_size;

    cudaFuncSetAttribute(gemm_qkv,  cudaFuncAttributeMaxDynamicSharedMemorySize, GSMEM);
    cudaFuncSetAttribute(gemm_proj, cudaFuncAttributeMaxDynamicSharedMemorySize, PSMEM);
    cudaFuncSetAttribute(attn_tc,   cudaFuncAttributeMaxDynamicSharedMemorySize, AT_SMEM);

    split_all<<<MROWS + 3 * DIM + DIM, 256>>>(x, w_qkv, w_proj);

    // QKV projection (128x64, 3 CTAs/SM)
    gemm_qkv<<<dim3(3 * DIM / 64, MROWS / 128), 256, GSMEM>>>();

    // attention
    attn_tc<<<dim3(SEQ / 128, NHEADS, BATCH), 256, AT_SMEM>>>();

    // output projection (128x128, 2 CTAs/SM, single wave)
    gemm_proj<<<dim3(DIM / 128, MROWS / 128), 256, PSMEM>>>(out);
}

// round 13
// speedup vs baseline: 2.8479x; 1.0328x over previous
#include <cuda_runtime.h>
#include <cuda_fp16.h>
#include <cstdint>

#define BATCH 2
#define SEQ 2048
#define DIM 1024
#define NHEADS 16
#define HDIM 64
#define QSCALE 0.1803368801111204f   // (1/8) * log2(e)
#define MROWS 4096

// ---------------------------------------------------------------------------
// Scratch (device globals: allocation-free)
// ---------------------------------------------------------------------------
__device__ __align__(16) __half g_xh [(size_t)MROWS * DIM];
__device__ __align__(16) __half g_wqh[(size_t)3 * DIM * DIM];
__device__ __align__(16) __half g_wph[(size_t)DIM * DIM];
__device__ __align__(16) __half g_aoh[(size_t)MROWS * DIM];

#define QKV_ELEMS ((size_t)BATCH * NHEADS * SEQ * HDIM)
__device__ __align__(16) __half g_q[QKV_ELEMS];   // pre-scaled by QSCALE
__device__ __align__(16) __half g_k[QKV_ELEMS];
__device__ __align__(16) __half g_v[QKV_ELEMS];

// ---------------------------------------------------------------------------
// Base-ISA helpers
// ---------------------------------------------------------------------------
__device__ __forceinline__ uint32_t smem_u32(const void* p) {
    uint32_t a;
    asm("{ .reg .u64 t; cvta.to.shared.u64 t, %1; cvt.u32.u64 %0, t; }"
        : "=r"(a) : "l"(p));
    return a;
}
__device__ __forceinline__ void ldsm4(uint32_t* r, uint32_t a) {
    asm volatile("ldmatrix.sync.aligned.m8n8.x4.shared.b16 {%0,%1,%2,%3}, [%4];"
        : "=r"(r[0]), "=r"(r[1]), "=r"(r[2]), "=r"(r[3]) : "r"(a));
}
__device__ __forceinline__ void ldsm4t(uint32_t* r, uint32_t a) {
    asm volatile("ldmatrix.sync.aligned.m8n8.x4.trans.shared.b16 {%0,%1,%2,%3}, [%4];"
        : "=r"(r[0]), "=r"(r[1]), "=r"(r[2]), "=r"(r[3]) : "r"(a));
}
__device__ __forceinline__ void mma_f16(float* c, const uint32_t* a, const uint32_t* b) {
    asm volatile(
        "mma.sync.aligned.m16n8k16.row.col.f32.f16.f16.f32 "
        "{%0,%1,%2,%3}, {%4,%5,%6,%7}, {%8,%9}, {%0,%1,%2,%3};"
        : "+f"(c[0]), "+f"(c[1]), "+f"(c[2]), "+f"(c[3])
        : "r"(a[0]), "r"(a[1]), "r"(a[2]), "r"(a[3]), "r"(b[0]), "r"(b[1]));
}
#define CPA16(d, s) \
    asm volatile("cp.async.cg.shared.global [%0], [%1], 16;" :: "r"(d), "l"(s))
#define CP_COMMIT() asm volatile("cp.async.commit_group;" ::: "memory")

__device__ __forceinline__ float ex2(float x) {
    float r; asm("ex2.approx.f32 %0, %1;" : "=f"(r) : "f"(x)); return r;
}
__device__ __forceinline__ uint32_t pack2h(float x, float y) {
    __half2 t = __floats2half2_rn(x, y);
    return *reinterpret_cast<uint32_t*>(&t);
}

// ---------------------------------------------------------------------------
// Merged split: one launch, 8 floats per thread.
// ---------------------------------------------------------------------------
#define XN  ((size_t)MROWS * DIM)        // 4M
#define WQN ((size_t)3 * DIM * DIM)      // 3M
#define WPN ((size_t)DIM * DIM)          // 1M

__global__ void split_all(const float* __restrict__ x,
                          const float* __restrict__ wq,
                          const float* __restrict__ wp)
{
    size_t idx = (size_t)blockIdx.x * 2048 + (size_t)threadIdx.x * 8;
    const float* src;
    __half* dst;
    if (idx < XN)            { src = x  + idx;             dst = g_xh  + idx; }
    else if (idx < XN + WQN) { src = wq + (idx - XN);      dst = g_wqh + (idx - XN); }
    else                     { src = wp + (idx - XN - WQN); dst = g_wph + (idx - XN - WQN); }
    float4 a = *(const float4*)(src);
    float4 b = *(const float4*)(src + 4);
    *(uint2*)(dst)     = make_uint2(pack2h(a.x, a.y), pack2h(a.z, a.w));
    *(uint2*)(dst + 4) = make_uint2(pack2h(b.x, b.y), pack2h(b.z, b.w));
}

// ---------------------------------------------------------------------------
// QKV GEMM (proven R12): CTA 128x64, 3 CTAs/SM, fused fp16 Q/K/V epilogue.
// ---------------------------------------------------------------------------
#define GST 24576
#define GBOFF 16384
#define GSMEM (3 * GST)
#define NCHT 16

__global__ __launch_bounds__(256, 3)
void gemm_qkv()
{
    extern __shared__ char sm[];
    const uint32_t sb = smem_u32(sm);
    const int tid = threadIdx.x, lane = tid & 31, wid = tid >> 5;
    const int wm = wid >> 1, wn = wid & 1;
    const int bm = blockIdx.y * 128, bn = blockIdx.x * 64;

    const int lra = tid >> 1;
    const int lca = (tid & 1) * 4;
    const int lrb = tid >> 2;
    const int lcb = (tid & 3) * 2;

    auto load_stage = [&](int ch, int s) {
        const int co = ch * 64;
        uint32_t abase = sb + s * GST + lra * 128;
        const __half* a = g_xh + (size_t)(bm + lra) * DIM + co;
#pragma unroll
        for (int i = 0; i < 4; i++) {
            int c16 = lca + i;
            CPA16(abase + (uint32_t)((c16 ^ (lra & 7)) << 4), a + c16 * 8);
        }
        uint32_t bbase = sb + s * GST + GBOFF + lrb * 128;
        const __half* b = g_wqh + (size_t)(bn + lrb) * DIM + co;
#pragma unroll
        for (int i = 0; i < 2; i++) {
            int c16 = lcb + i;
            CPA16(bbase + (uint32_t)((c16 ^ (lrb & 7)) << 4), b + c16 * 8);
        }
        CP_COMMIT();
    };

    load_stage(0, 0);
    load_stage(1, 1);

    float acc[2][4][4];
#pragma unroll
    for (int i = 0; i < 2; i++)
#pragma unroll
        for (int j = 0; j < 4; j++)
#pragma unroll
            for (int q = 0; q < 4; q++) acc[i][j][q] = 0.f;

    const int arow0 = wm * 32 + (lane & 15);
    const int alc = lane >> 4;
    const int brow0 = wn * 32 + ((lane >> 4) & 1) * 8 + (lane & 7);
    const int bc = (lane >> 3) & 1;

    for (int ch = 0; ch < NCHT; ch++) {
        const int s = ch % 3;
        if (ch + 1 < NCHT) { asm volatile("cp.async.wait_group 1;" ::: "memory"); }
        else               { asm volatile("cp.async.wait_group 0;" ::: "memory"); }
        __syncthreads();
        const uint32_t Ab = sb + s * GST;
        const uint32_t Bb = Ab + GBOFF;
#pragma unroll
        for (int kk = 0; kk < 4; kk++) {
            uint32_t a0[4], a1[4];
            {
                int c = kk * 2 + alc;
                int r0 = arow0;
                ldsm4(a0, Ab + r0 * 128 + ((c ^ (r0 & 7)) << 4));
                int r1 = arow0 + 16;
                ldsm4(a1, Ab + r1 * 128 + ((c ^ (r1 & 7)) << 4));
            }
#pragma unroll
            for (int bp = 0; bp < 2; bp++) {
                uint32_t b[4];
                int r = brow0 + bp * 16;
                int c = kk * 2 + bc;
                ldsm4(b, Bb + r * 128 + ((c ^ (r & 7)) << 4));
                mma_f16(acc[0][2 * bp],     a0, b);
                mma_f16(acc[0][2 * bp + 1], a0, b + 2);
                mma_f16(acc[1][2 * bp],     a1, b);
                mma_f16(acc[1][2 * bp + 1], a1, b + 2);
            }
        }
        if (ch + 2 < NCHT) load_stage(ch + 2, (ch + 2) % 3);
    }

    const int g = lane >> 2, t = lane & 3;
    int col0 = bn + wn * 32;
    int mat = col0 >> 10;
    int cm = col0 & 1023;
    int hh = cm >> 6;
    int d0 = cm & 63;
    __half* BQ = (mat == 0) ? g_q : (mat == 1) ? g_k : g_v;
    const float qs = (mat == 0) ? QSCALE : 1.0f;
#pragma unroll
    for (int mf = 0; mf < 2; mf++) {
        int rg = bm + wm * 32 + mf * 16 + g;
        int bb = rg >> 11, l = rg & 2047;
        size_t base = ((size_t)(bb * NHEADS + hh) * SEQ + l) * HDIM;
#pragma unroll
        for (int nf = 0; nf < 4; nf++) {
            int d = d0 + nf * 8 + t * 2;
            *(uint32_t*)(BQ + base + d) =
                pack2h(acc[mf][nf][0] * qs, acc[mf][nf][1] * qs);
            *(uint32_t*)(BQ + base + 8 * HDIM + d) =
                pack2h(acc[mf][nf][2] * qs, acc[mf][nf][3] * qs);
        }
    }
}

// ---------------------------------------------------------------------------
// Proj GEMM (proven R12): CTA 128x128, 2 CTAs/SM, single wave.
// ---------------------------------------------------------------------------
#define PST 32768
#define PBOFF 16384
#define PSMEM (3 * PST)

__global__ __launch_bounds__(256, 2)
void gemm_proj(float* __restrict__ Cout)
{
    const int N = DIM;
    extern __shared__ char sm[];
    const uint32_t sb = smem_u32(sm);
    const int tid = threadIdx.x, lane = tid & 31, wid = tid >> 5;
    const int wm = wid >> 1, wn = wid & 1;
    const int bm = blockIdx.y * 128, bn = blockIdx.x * 128;

    const int ldrow = tid >> 1;
    const int ldc0 = (tid & 1) * 4;

    auto load_stage = [&](int ch, int s) {
        const __half* a = g_aoh + (size_t)(bm + ldrow) * DIM + ch * 64;
        const __half* b = g_wph + (size_t)(bn + ldrow) * DIM + ch * 64;
        uint32_t rbase = sb + s * PST + ldrow * 128;
#pragma unroll
        for (int i = 0; i < 4; i++) {
            int c16 = ldc0 + i;
            uint32_t sw = rbase + (uint32_t)((c16 ^ (ldrow & 7)) << 4);
            CPA16(sw, a + c16 * 8);
            CPA16(sw + PBOFF, b + c16 * 8);
        }
        CP_COMMIT();
    };

    load_stage(0, 0);
    load_stage(1, 1);

    float acc[2][8][4];
#pragma unroll
    for (int i = 0; i < 2; i++)
#pragma unroll
        for (int j = 0; j < 8; j++)
#pragma unroll
            for (int q = 0; q < 4; q++) acc[i][j][q] = 0.f;

    const int arow0 = wm * 32 + (lane & 15);
    const int alc = lane >> 4;
    const int brow0 = wn * 64 + ((lane >> 4) & 1) * 8 + (lane & 7);
    const int bc = (lane >> 3) & 1;

    for (int ch = 0; ch < NCHT; ch++) {
        const int s = ch % 3;
        if (ch + 1 < NCHT) { asm volatile("cp.async.wait_group 1;" ::: "memory"); }
        else               { asm volatile("cp.async.wait_group 0;" ::: "memory"); }
        __syncthreads();
        const uint32_t Ab = sb + s * PST;
        const uint32_t Bb = Ab + PBOFF;
#pragma unroll
        for (int kk = 0; kk < 4; kk++) {
            uint32_t a0[4], a1[4];
            {
                int c = kk * 2 + alc;
                int r0 = arow0;
                ldsm4(a0, Ab + r0 * 128 + ((c ^ (r0 & 7)) << 4));
                int r1 = arow0 + 16;
                ldsm4(a1, Ab + r1 * 128 + ((c ^ (r1 & 7)) << 4));
            }
#pragma unroll
            for (int bp = 0; bp < 4; bp++) {
                uint32_t b[4];
                int r = brow0 + bp * 16;
                int c = kk * 2 + bc;
                ldsm4(b, Bb + r * 128 + ((c ^ (r & 7)) << 4));
                mma_f16(acc[0][2 * bp],     a0, b);
                mma_f16(acc[0][2 * bp + 1], a0, b + 2);
                mma_f16(acc[1][2 * bp],     a1, b);
                mma_f16(acc[1][2 * bp + 1], a1, b + 2);
            }
        }
        if (ch + 2 < NCHT) load_stage(ch + 2, (ch + 2) % 3);
    }

    const int g = lane >> 2, t = lane & 3;
#pragma unroll
    for (int mf = 0; mf < 2; mf++) {
        int row = bm + wm * 32 + mf * 16 + g;
#pragma unroll
        for (int nf = 0; nf < 8; nf++) {
            int col = bn + wn * 64 + nf * 8 + t * 2;
            *(float2*)(Cout + (size_t)row * N + col) =
                make_float2(acc[mf][nf][0], acc[mf][nf][1]);
            *(float2*)(Cout + (size_t)(row + 8) * N + col) =
                make_float2(acc[mf][nf][2], acc[mf][nf][3]);
        }
    }
}

// ---------------------------------------------------------------------------
// Flash attention: 3-stage ring of 128-row KV tiles (halves barrier count).
// smem: 3 x 32KB stages (K 16KB | V 16KB) + Q 16KB at 96KB = 112KB.
// Per stage, compute runs over two 64-row sub-tiles (registers unchanged).
// ---------------------------------------------------------------------------
#define AT_SMEM 114688
#define NIT2 (SEQ / 128)      // 16

__global__ __launch_bounds__(256, 2)
void attn_tc()
{
    extern __shared__ char smem[];
    const uint32_t sb = smem_u32(smem);
    const int tid = threadIdx.x, lane = tid & 31, wid = tid >> 5;
    const int b = blockIdx.z, h = blockIdx.y, q0 = blockIdx.x * 128;
    const size_t bh = (size_t)(b * NHEADS + h) * SEQ;

    // ---- stage Q (128x64 fp16 = 16 KB) ----
    const uint32_t QB = sb + 3 * 32768;
    {
        const __half* src = g_q + (bh + q0) * HDIM;
#pragma unroll
        for (int i = 0; i < 4; i++) {
            int idx = i * 256 + tid;
            int row = idx >> 3, c16 = idx & 7;
            uint32_t sw = QB + row * 128 + ((c16 ^ (row & 7)) << 4);
            CPA16(sw, src + (size_t)row * HDIM + c16 * 8);
        }
        CP_COMMIT();
        asm volatile("cp.async.wait_group 0;" ::: "memory");
    }
    __syncthreads();

    uint32_t qf[4][4];
    {
        int r = wid * 16 + (lane & 15);
        int cl = lane >> 4;
#pragma unroll
        for (int kk = 0; kk < 4; kk++)
            ldsm4(qf[kk], QB + r * 128 + (((kk * 2 + cl) ^ (r & 7)) << 4));
    }

    // load one 128-row KV stage (K 16KB + V 16KB)
    auto load_kv = [&](int it, int s) {
        const size_t rb = bh + (size_t)it * 128;
        uint32_t dst = sb + s * 32768;
#pragma unroll
        for (int i = 0; i < 4; i++) {
            int idx = i * 256 + tid;          // 0..1023
            int row = idx >> 3, c16 = idx & 7;
            uint32_t sw = dst + row * 128 + ((c16 ^ (row & 7)) << 4);
            CPA16(sw, g_k + (rb + row) * HDIM + c16 * 8);
            CPA16(sw + 16384, g_v + (rb + row) * HDIM + c16 * 8);
        }
        CP_COMMIT();
    };

    load_kv(0, 0);
    load_kv(1, 1);

    float o[8][4];
#pragma unroll
    for (int i = 0; i < 8; i++)
#pragma unroll
        for (int j = 0; j < 4; j++) o[i][j] = 0.f;
    float m0 = -1e30f, m1 = -1e30f, l0s = 0.f, l1s = 0.f;

    const int brow0 = ((lane >> 4) & 1) * 8 + (lane & 7);
    const int bc = (lane >> 3) & 1;
    const int vlc = lane >> 4;

    for (int it = 0; it < NIT2; it++) {
        const int s = it % 3;
        if (it + 1 < NIT2) { asm volatile("cp.async.wait_group 1;" ::: "memory"); }
        else               { asm volatile("cp.async.wait_group 0;" ::: "memory"); }
        __syncthreads();
        if (it + 2 < NIT2) load_kv(it + 2, (it + 2) % 3);

#pragma unroll
        for (int sub = 0; sub < 2; sub++) {
            const uint32_t KB = sb + s * 32768 + sub * 8192;
            const uint32_t VB = sb + s * 32768 + 16384 + sub * 8192;

            // ---- S = Q K^T (exp2 domain via pre-scaled Q) ----
            float sx[8][4];
#pragma unroll
            for (int i = 0; i < 8; i++)
#pragma unroll
                for (int j = 0; j < 4; j++) sx[i][j] = 0.f;
#pragma unroll
            for (int kk = 0; kk < 4; kk++) {
#pragma unroll
                for (int bp = 0; bp < 4; bp++) {
                    uint32_t kfrag[4];
                    int r = brow0 + bp * 16;
                    int c = kk * 2 + bc;
                    ldsm4(kfrag, KB + r * 128 + ((c ^ (r & 7)) << 4));
                    mma_f16(sx[2 * bp],     qf[kk], kfrag);
                    mma_f16(sx[2 * bp + 1], qf[kk], kfrag + 2);
                }
            }

            // ---- online softmax ----
            float rmax0 = -1e30f, rmax1 = -1e30f;
#pragma unroll
            for (int nf = 0; nf < 8; nf++) {
                rmax0 = fmaxf(rmax0, fmaxf(sx[nf][0], sx[nf][1]));
                rmax1 = fmaxf(rmax1, fmaxf(sx[nf][2], sx[nf][3]));
            }
            rmax0 = fmaxf(rmax0, __shfl_xor_sync(0xffffffffu, rmax0, 1));
            rmax0 = fmaxf(rmax0, __shfl_xor_sync(0xffffffffu, rmax0, 2));
            rmax1 = fmaxf(rmax1, __shfl_xor_sync(0xffffffffu, rmax1, 1));
            rmax1 = fmaxf(rmax1, __shfl_xor_sync(0xffffffffu, rmax1, 2));
            float mn0 = fmaxf(m0, rmax0), mn1 = fmaxf(m1, rmax1);
            float corr0 = ex2(m0 - mn0), corr1 = ex2(m1 - mn1);
            float sum0 = 0.f, sum1 = 0.f;
#pragma unroll
            for (int nf = 0; nf < 8; nf++) {
                sx[nf][0] = ex2(sx[nf][0] - mn0);
                sx[nf][1] = ex2(sx[nf][1] - mn0);
                sx[nf][2] = ex2(sx[nf][2] - mn1);
                sx[nf][3] = ex2(sx[nf][3] - mn1);
                sum0 += sx[nf][0] + sx[nf][1];
                sum1 += sx[nf][2] + sx[nf][3];
            }
            sum0 += __shfl_xor_sync(0xffffffffu, sum0, 1);
            sum0 += __shfl_xor_sync(0xffffffffu, sum0, 2);
            sum1 += __shfl_xor_sync(0xffffffffu, sum1, 1);
            sum1 += __shfl_xor_sync(0xffffffffu, sum1, 2);
            l0s = l0s * corr0 + sum0;
            l1s = l1s * corr1 + sum1;
            m0 = mn0; m1 = mn1;
#pragma unroll
            for (int nf = 0; nf < 8; nf++) {
                o[nf][0] *= corr0; o[nf][1] *= corr0;
                o[nf][2] *= corr1; o[nf][3] *= corr1;
            }

            // ---- O += P V ----
#pragma unroll
            for (int kk = 0; kk < 4; kk++) {
                uint32_t pf[4];
                pf[0] = pack2h(sx[2 * kk][0], sx[2 * kk][1]);
                pf[1] = pack2h(sx[2 * kk][2], sx[2 * kk][3]);
                pf[2] = pack2h(sx[2 * kk + 1][0], sx[2 * kk + 1][1]);
                pf[3] = pack2h(sx[2 * kk + 1][2], sx[2 * kk + 1][3]);
#pragma unroll
                for (int hp = 0; hp < 4; hp++) {
                    uint32_t vf[4];
                    int r = kk * 16 + ((lane >> 3) & 1) * 8 + (lane & 7);
                    int c = hp * 2 + vlc;
                    ldsm4t(vf, VB + r * 128 + ((c ^ (r & 7)) << 4));
                    mma_f16(o[2 * hp],     pf, vf);
                    mma_f16(o[2 * hp + 1], pf, vf + 2);
                }
            }
        }
    }

    // ---- epilogue: fp16 proj operand ----
    const int g = lane >> 2, t = lane & 3;
    float inv0 = 1.f / l0s, inv1 = 1.f / l1s;
    size_t arow0 = (size_t)b * SEQ + q0 + wid * 16 + g;
#pragma unroll
    for (int nf = 0; nf < 8; nf++) {
        int col = h * 64 + nf * 8 + t * 2;
        *(uint32_t*)(g_aoh + arow0 * DIM + col) =
            pack2h(o[nf][0] * inv0, o[nf][1] * inv0);
        *(uint32_t*)(g_aoh + (arow0 + 8) * DIM + col) =
            pack2h(o[nf][2] * inv1, o[nf][3] * inv1);
    }
}

// ---------------------------------------------------------------------------
// Launch
// ---------------------------------------------------------------------------
extern "C" void kernel_launch(void* const* d_in, const int* in_sizes, int n_in,
                              void* d_out, int out_size)
{
    const float* x      = (const float*)d_in[0];
    const float* w_qkv  = (const float*)d_in[1];
    const float* w_proj = (const float*)d_in[2];
    float* out = (float*)d_out;
    (void)in_sizes; (void)n_in; (void)out_size;

    cudaFuncSetAttribute(gemm_qkv,  cudaFuncAttributeMaxDynamicSharedMemorySize, GSMEM);
    cudaFuncSetAttribute(gemm_proj, cudaFuncAttributeMaxDynamicSharedMemorySize, PSMEM);
    cudaFuncSetAttribute(attn_tc,   cudaFuncAttributeMaxDynamicSharedMemorySize, AT_SMEM);

    // merged fp32 -> fp16 conversion: 8M elements / 2048 per block
    split_all<<<4096, 256>>>(x, w_qkv, w_proj);

    // QKV projection (128x64, 3 CTAs/SM)
    gemm_qkv<<<dim3(3 * DIM / 64, MROWS / 128), 256, GSMEM>>>();

    // attention (128-row KV stages, 3-stage ring)
    attn_tc<<<dim3(SEQ / 128, NHEADS, BATCH), 256, AT_SMEM>>>();

    // output projection (128x128, 2 CTAs/SM, single wave)
    gemm_proj<<<dim3(DIM / 128, MROWS / 128), 256, PSMEM>>>(out);
}